// round 2
// baseline (speedup 1.0000x reference)
#include <cuda_runtime.h>
#include <cuda_bf16.h>

#define BB 8
#define SS 1024
#define EE 768
#define HH 12
#define PP 64

// Scratch (allocation-free rule: __device__ globals)
__device__ float g_K [BB*HH*SS*PP];   // [b][h][s][p]
__device__ float g_V [BB*HH*SS*PP];   // [b][h][s][p]
__device__ float g_QV[BB*HH*SS*PP];   // [b][h][s][p]
__device__ float g_At[BB*SS*HH*PP];   // [b][s][h][p]  (row-major 8192 x 768)

// ---------------------------------------------------------------------------
// Kernel 1: K = X @ Wk, V = X @ Wv   (shared X tile, two outputs)
// grid (S/64, H, B), 256 threads, 64x64 tile, BK=16, 4x4 micro
// ---------------------------------------------------------------------------
__global__ __launch_bounds__(256) void proj_kernel(
    const float* __restrict__ x, const float* __restrict__ wk,
    const float* __restrict__ wv)
{
    const int it = blockIdx.x, h = blockIdx.y, b = blockIdx.z;
    const int i0 = it * 64;
    __shared__ float Xs[16][64];
    __shared__ float Ks[16][64];
    __shared__ float Vs[16][64];

    const int tid = threadIdx.x;
    const int tx = tid & 15, ty = tid >> 4;
    float accK[4][4] = {}, accV[4][4] = {};

    const float* xb = x + (b * SS + i0) * EE;

    for (int e0 = 0; e0 < EE; e0 += 16) {
        #pragma unroll
        for (int t = 0; t < 4; t++) {
            int li = tid + t * 256;
            int m = li >> 4, kk = li & 15;
            Xs[kk][m] = xb[m * EE + e0 + kk];
        }
        #pragma unroll
        for (int t = 0; t < 4; t++) {
            int li = tid + t * 256;
            int kk = li >> 6, p = li & 63;
            Ks[kk][p] = wk[(h * EE + e0 + kk) * PP + p];
            Vs[kk][p] = wv[(h * EE + e0 + kk) * PP + p];
        }
        __syncthreads();
        #pragma unroll
        for (int kk = 0; kk < 16; kk++) {
            float4 af = *(const float4*)&Xs[kk][ty * 4];
            float4 bk = *(const float4*)&Ks[kk][tx * 4];
            float4 bv = *(const float4*)&Vs[kk][tx * 4];
            float a[4] = {af.x, af.y, af.z, af.w};
            float k4[4] = {bk.x, bk.y, bk.z, bk.w};
            float v4[4] = {bv.x, bv.y, bv.z, bv.w};
            #pragma unroll
            for (int r = 0; r < 4; r++)
                #pragma unroll
                for (int c = 0; c < 4; c++) {
                    accK[r][c] = fmaf(a[r], k4[c], accK[r][c]);
                    accV[r][c] = fmaf(a[r], v4[c], accV[r][c]);
                }
        }
        __syncthreads();
    }
    const int base = ((b * HH + h) * SS + i0) * PP;
    #pragma unroll
    for (int r = 0; r < 4; r++) {
        int row = ty * 4 + r;
        *(float4*)&g_K[base + row * PP + tx * 4] =
            make_float4(accK[r][0], accK[r][1], accK[r][2], accK[r][3]);
        *(float4*)&g_V[base + row * PP + tx * 4] =
            make_float4(accV[r][0], accV[r][1], accV[r][2], accV[r][3]);
    }
}

// ---------------------------------------------------------------------------
// Kernel 2: QV = Q_h @ V   (1024x1024)@(1024x64) per (b,h)
// ---------------------------------------------------------------------------
__global__ __launch_bounds__(256) void qv_kernel(const float* __restrict__ q)
{
    const int it = blockIdx.x, h = blockIdx.y, b = blockIdx.z;
    const int i0 = it * 64;
    __shared__ float As[16][64];
    __shared__ float Bs[16][64];

    const int tid = threadIdx.x;
    const int tx = tid & 15, ty = tid >> 4;
    float acc[4][4] = {};

    const float* qb = q + (h * SS + i0) * SS;
    const float* vb = g_V + ((b * HH + h) * SS) * PP;

    for (int j0 = 0; j0 < SS; j0 += 16) {
        #pragma unroll
        for (int t = 0; t < 4; t++) {
            int li = tid + t * 256;
            int m = li >> 4, kk = li & 15;
            As[kk][m] = qb[m * SS + j0 + kk];
        }
        #pragma unroll
        for (int t = 0; t < 4; t++) {
            int li = tid + t * 256;
            int kk = li >> 6, p = li & 63;
            Bs[kk][p] = vb[(j0 + kk) * PP + p];
        }
        __syncthreads();
        #pragma unroll
        for (int kk = 0; kk < 16; kk++) {
            float4 af = *(const float4*)&As[kk][ty * 4];
            float4 bf = *(const float4*)&Bs[kk][tx * 4];
            float a[4] = {af.x, af.y, af.z, af.w};
            float bv[4] = {bf.x, bf.y, bf.z, bf.w};
            #pragma unroll
            for (int r = 0; r < 4; r++)
                #pragma unroll
                for (int c = 0; c < 4; c++)
                    acc[r][c] = fmaf(a[r], bv[c], acc[r][c]);
        }
        __syncthreads();
    }
    const int base = ((b * HH + h) * SS + i0) * PP;
    #pragma unroll
    for (int r = 0; r < 4; r++) {
        int row = ty * 4 + r;
        *(float4*)&g_QV[base + row * PP + tx * 4] =
            make_float4(acc[r][0], acc[r][1], acc[r][2], acc[r][3]);
    }
}

// ---------------------------------------------------------------------------
// Kernel 3: causal masked softmax attention, flash-style, max-free
//   score[i,j] = K[i]·QV[j]/sqrt(E),  j<=i
//   attn[i,:] = sum_j exp(score)/l * V[j,:]
// Output to g_At in [b][s][h][p] layout.
// Dynamic smem: ks 64x68, qs(->ps) 64x68, vs 64x64  = 51200 B
// ---------------------------------------------------------------------------
#define LDK 68
__global__ __launch_bounds__(256) void attn_kernel()
{
    extern __shared__ float sm[];
    float* ks = sm;                // 64*68
    float* qs = sm + 64 * LDK;     // 64*68, reused as P tile
    float* vs = sm + 2 * 64 * LDK; // 64*64

    const int it = blockIdx.x, h = blockIdx.y, b = blockIdx.z;
    const int i0 = it * 64;
    const int tid = threadIdx.x;
    const int tx = tid & 15, ty = tid >> 4;
    const int ty4 = ty * 4, tx4 = tx * 4;
    const float scale = 0.03608439182435161f;  // 1/sqrt(768)

    const int bh = (b * HH + h) * SS;
    const float* Kb  = g_K  + bh * PP;
    const float* QVb = g_QV + bh * PP;
    const float* Vb  = g_V  + bh * PP;

    // load K tile for this row block (lives whole kernel)
    #pragma unroll
    for (int t = 0; t < 16; t++) {
        int idx = tid + t * 256;
        int r = idx >> 6, p = idx & 63;
        ks[r * LDK + p] = Kb[(i0 + r) * PP + p];
    }

    float O[4][4] = {};
    float l[4] = {};

    for (int jt = 0; jt <= it; jt++) {
        const int j0 = jt * 64;
        #pragma unroll
        for (int t = 0; t < 16; t++) {
            int idx = tid + t * 256;
            int r = idx >> 6, p = idx & 63;
            qs[r * LDK + p] = QVb[(j0 + r) * PP + p];
            vs[r * 64  + p] = Vb [(j0 + r) * PP + p];
        }
        __syncthreads();

        // S[r][c] = sum_p ks[ty4+r][p] * qs[tx4+c][p]
        float Sv[4][4] = {};
        #pragma unroll 4
        for (int p = 0; p < 64; p += 4) {
            float4 ka[4], qa[4];
            #pragma unroll
            for (int r = 0; r < 4; r++) ka[r] = *(const float4*)&ks[(ty4 + r) * LDK + p];
            #pragma unroll
            for (int c = 0; c < 4; c++) qa[c] = *(const float4*)&qs[(tx4 + c) * LDK + p];
            #pragma unroll
            for (int r = 0; r < 4; r++)
                #pragma unroll
                for (int c = 0; c < 4; c++)
                    Sv[r][c] += ka[r].x * qa[c].x + ka[r].y * qa[c].y +
                                ka[r].z * qa[c].z + ka[r].w * qa[c].w;
        }
        __syncthreads();  // done reading qs; about to overwrite as P tile

        // mask + exp; accumulate partial row sums; write P tile
        #pragma unroll
        for (int r = 0; r < 4; r++) {
            int i = i0 + ty4 + r;
            #pragma unroll
            for (int c = 0; c < 4; c++) {
                int j = j0 + tx4 + c;
                float e = (j <= i) ? __expf(Sv[r][c] * scale) : 0.0f;
                l[r] += e;
                qs[(ty4 + r) * LDK + (tx4 + c)] = e;
            }
        }
        __syncthreads();

        // O[r][c] += sum_j P[ty4+r][j] * vs[j][tx4+c]
        #pragma unroll 4
        for (int j = 0; j < 64; j += 4) {
            float4 pa[4], va[4];
            #pragma unroll
            for (int r = 0; r < 4; r++) pa[r] = *(const float4*)&qs[(ty4 + r) * LDK + j];
            #pragma unroll
            for (int jj = 0; jj < 4; jj++) va[jj] = *(const float4*)&vs[(j + jj) * 64 + tx4];
            #pragma unroll
            for (int r = 0; r < 4; r++) {
                float pv[4] = {pa[r].x, pa[r].y, pa[r].z, pa[r].w};
                #pragma unroll
                for (int jj = 0; jj < 4; jj++) {
                    O[r][0] = fmaf(pv[jj], va[jj].x, O[r][0]);
                    O[r][1] = fmaf(pv[jj], va[jj].y, O[r][1]);
                    O[r][2] = fmaf(pv[jj], va[jj].z, O[r][2]);
                    O[r][3] = fmaf(pv[jj], va[jj].w, O[r][3]);
                }
            }
        }
        __syncthreads();  // done with qs/vs before next tile load
    }

    // reduce l across the 16 threads sharing each row (contiguous 16-lane groups)
    #pragma unroll
    for (int r = 0; r < 4; r++) {
        #pragma unroll
        for (int m = 8; m >= 1; m >>= 1)
            l[r] += __shfl_xor_sync(0xffffffffu, l[r], m, 16);
    }

    // write attn in [b][s][h][p] layout
    #pragma unroll
    for (int r = 0; r < 4; r++) {
        int i = i0 + ty4 + r;
        float inv = 1.0f / l[r];
        *(float4*)&g_At[((b * SS + i) * HH + h) * PP + tx4] =
            make_float4(O[r][0] * inv, O[r][1] * inv, O[r][2] * inv, O[r][3] * inv);
    }
}

// ---------------------------------------------------------------------------
// Kernel 4: out = attn(8192x768) @ lifting(768x768)
// grid (E/64, B*S/64)
// ---------------------------------------------------------------------------
__global__ __launch_bounds__(256) void lift_kernel(
    const float* __restrict__ lift, float* __restrict__ out)
{
    const int n0 = blockIdx.x * 64;
    const int m0 = blockIdx.y * 64;
    __shared__ float As[16][64];
    __shared__ float Bs[16][64];

    const int tid = threadIdx.x;
    const int tx = tid & 15, ty = tid >> 4;
    float acc[4][4] = {};

    for (int k0 = 0; k0 < EE; k0 += 16) {
        #pragma unroll
        for (int t = 0; t < 4; t++) {
            int li = tid + t * 256;
            int m = li >> 4, kk = li & 15;
            As[kk][m] = g_At[(m0 + m) * EE + k0 + kk];
        }
        #pragma unroll
        for (int t = 0; t < 4; t++) {
            int li = tid + t * 256;
            int kk = li >> 6, n = li & 63;
            Bs[kk][n] = lift[(k0 + kk) * EE + n0 + n];
        }
        __syncthreads();
        #pragma unroll
        for (int kk = 0; kk < 16; kk++) {
            float4 af = *(const float4*)&As[kk][ty * 4];
            float4 bf = *(const float4*)&Bs[kk][tx * 4];
            float a[4] = {af.x, af.y, af.z, af.w};
            float bv[4] = {bf.x, bf.y, bf.z, bf.w};
            #pragma unroll
            for (int r = 0; r < 4; r++)
                #pragma unroll
                for (int c = 0; c < 4; c++)
                    acc[r][c] = fmaf(a[r], bv[c], acc[r][c]);
        }
        __syncthreads();
    }
    #pragma unroll
    for (int r = 0; r < 4; r++) {
        int row = m0 + ty * 4 + r;
        *(float4*)&out[row * EE + n0 + tx * 4] =
            make_float4(acc[r][0], acc[r][1], acc[r][2], acc[r][3]);
    }
}

// ---------------------------------------------------------------------------
extern "C" void kernel_launch(void* const* d_in, const int* in_sizes, int n_in,
                              void* d_out, int out_size)
{
    const float* x    = (const float*)d_in[0];  // (B,1,S,E)
    const float* wk   = (const float*)d_in[1];  // (H,E,P)
    const float* wv   = (const float*)d_in[2];  // (H,E,P)
    const float* q    = (const float*)d_in[3];  // (H,S,S)
    const float* lift = (const float*)d_in[4];  // (1,H*P,E)
    float* out = (float*)d_out;                 // (B,S,E)

    cudaFuncSetAttribute(attn_kernel,
                         cudaFuncAttributeMaxDynamicSharedMemorySize, 64 * 1024);

    dim3 g(SS / 64, HH, BB);
    proj_kernel<<<g, 256>>>(x, wk, wv);
    qv_kernel<<<g, 256>>>(q);
    attn_kernel<<<g, 256, 3 * 64 * LDK * 4 - 64 * (LDK - 64) * 4>>>();  // 51200 B
    dim3 g4(EE / 64, (BB * SS) / 64);
    lift_kernel<<<g4, 256>>>(lift, out);
}

// round 3
// speedup vs baseline: 1.2705x; 1.2705x over previous
#include <cuda_runtime.h>
#include <cuda_bf16.h>
#include <cstdint>

#define BB 8
#define SS 1024
#define EE 768
#define HH 12
#define PP 64

// Scratch (allocation-free rule: __device__ globals). All row-major 8192x768,
// logical layout [b][s][h][p].
__device__ float g_K [BB*SS*EE];
__device__ float g_V [BB*SS*EE];
__device__ float g_QV[BB*SS*EE];
__device__ float g_At[BB*SS*EE];

// ---------------------------------------------------------------------------
// TF32 mma helpers
// ---------------------------------------------------------------------------
__device__ __forceinline__ uint32_t f2tf32(float f) {
    uint32_t u;
    asm("cvt.rna.tf32.f32 %0, %1;" : "=r"(u) : "f"(f));
    return u;
}

__device__ __forceinline__ void mma_tf32(float c[4], const uint32_t a[4],
                                         const uint32_t b[2]) {
    asm volatile(
        "mma.sync.aligned.m16n8k8.row.col.f32.tf32.tf32.f32 "
        "{%0,%1,%2,%3}, {%4,%5,%6,%7}, {%8,%9}, {%0,%1,%2,%3};"
        : "+f"(c[0]), "+f"(c[1]), "+f"(c[2]), "+f"(c[3])
        : "r"(a[0]), "r"(a[1]), "r"(a[2]), "r"(a[3]), "r"(b[0]), "r"(b[1]));
}

// SMEM tile geometry
#define BM 128
#define BN 128
#define BK 32
#define LDA 36    // A tile row stride (floats), conflict-free for frag loads
#define LDB 136   // B tile row stride (floats), conflict-free for frag loads

// ---------------------------------------------------------------------------
// Generic TF32 GEMM: C(MxN) = A(MxK) @ B(KxN)
// BMODE 0: B plain row-major ldb.   BMODE 1: B head-packed: B[k][n] =
//          w[(n>>6)*K*64 + k*64 + (n&63)]  (w is [H][E][P])
// C written plain row-major ldc.
// grid: (N/BN, M/BM); 256 threads.
// ---------------------------------------------------------------------------
template <int BMODE>
__global__ __launch_bounds__(256) void gemm_tf32_kernel(
    const float* __restrict__ A, const float* __restrict__ Bm,
    float* __restrict__ C, int M, int N, int K, int lda, int ldb, int ldc)
{
    __shared__ uint32_t As[BM * LDA];
    __shared__ uint32_t Bs[BK * LDB];

    const int tid = threadIdx.x;
    const int wid = tid >> 5, lane = tid & 31;
    const int gid = lane >> 2, tig = lane & 3;     // groupID, threadID-in-group
    const int warp_m = (wid >> 2) * 64;            // 0 or 64
    const int warp_n = (wid & 3) * 32;             // 0,32,64,96
    const int m0 = blockIdx.y * BM, n0 = blockIdx.x * BN;

    float acc[4][4][4] = {};

    for (int k0 = 0; k0 < K; k0 += BK) {
        // ---- load A tile (BM x BK) as float4
        #pragma unroll
        for (int i = 0; i < 4; i++) {
            int f4 = tid + i * 256;              // 1024 float4 total
            int m = f4 >> 3, kc = (f4 & 7) * 4;
            float4 v = *(const float4*)&A[(m0 + m) * lda + k0 + kc];
            uint32_t* d = &As[m * LDA + kc];
            d[0] = f2tf32(v.x); d[1] = f2tf32(v.y);
            d[2] = f2tf32(v.z); d[3] = f2tf32(v.w);
        }
        // ---- load B tile (BK x BN)
        #pragma unroll
        for (int i = 0; i < 4; i++) {
            int f4 = tid + i * 256;
            int k = f4 >> 5, nc = (f4 & 31) * 4;
            const float* src;
            if (BMODE == 0) {
                src = &Bm[(k0 + k) * ldb + n0 + nc];
            } else {
                int n = n0 + nc;
                src = &Bm[(n >> 6) * (K * 64) + (k0 + k) * 64 + (n & 63)];
            }
            float4 v = *(const float4*)src;
            uint32_t* d = &Bs[k * LDB + nc];
            d[0] = f2tf32(v.x); d[1] = f2tf32(v.y);
            d[2] = f2tf32(v.z); d[3] = f2tf32(v.w);
        }
        __syncthreads();

        #pragma unroll
        for (int ks = 0; ks < BK / 8; ks++) {
            uint32_t af[4][4], bf[4][2];
            #pragma unroll
            for (int mt = 0; mt < 4; mt++) {
                int r = warp_m + mt * 16 + gid;
                int c = ks * 8 + tig;
                af[mt][0] = As[r * LDA + c];
                af[mt][1] = As[(r + 8) * LDA + c];
                af[mt][2] = As[r * LDA + c + 4];
                af[mt][3] = As[(r + 8) * LDA + c + 4];
            }
            #pragma unroll
            for (int nt = 0; nt < 4; nt++) {
                int k = ks * 8 + tig;
                int n = warp_n + nt * 8 + gid;
                bf[nt][0] = Bs[k * LDB + n];
                bf[nt][1] = Bs[(k + 4) * LDB + n];
            }
            #pragma unroll
            for (int mt = 0; mt < 4; mt++)
                #pragma unroll
                for (int nt = 0; nt < 4; nt++)
                    mma_tf32(acc[mt][nt], af[mt], bf[nt]);
        }
        __syncthreads();
    }

    // ---- epilogue
    #pragma unroll
    for (int mt = 0; mt < 4; mt++) {
        int r = m0 + warp_m + mt * 16 + gid;
        #pragma unroll
        for (int nt = 0; nt < 4; nt++) {
            int c = n0 + warp_n + nt * 8 + tig * 2;
            *(float2*)&C[r * ldc + c] = make_float2(acc[mt][nt][0], acc[mt][nt][1]);
            *(float2*)&C[(r + 8) * ldc + c] = make_float2(acc[mt][nt][2], acc[mt][nt][3]);
        }
    }
}

// ---------------------------------------------------------------------------
// QV GEMM per head: QV_cat(1024 x 512) = Q_h(1024x1024) @ Vcat(1024x512)
//   Vcat[j][n] = g_V[((n>>6)*SS + j)*EE + h*PP + (n&63)]
//   C[i][n]   -> g_QV[((n>>6)*SS + i)*EE + h*PP + (n&63)]
// grid: (512/BN, 1024/BM, H)
// ---------------------------------------------------------------------------
__global__ __launch_bounds__(256) void qv_tf32_kernel(const float* __restrict__ q)
{
    __shared__ uint32_t As[BM * LDA];
    __shared__ uint32_t Bs[BK * LDB];

    const int h = blockIdx.z;
    const int tid = threadIdx.x;
    const int wid = tid >> 5, lane = tid & 31;
    const int gid = lane >> 2, tig = lane & 3;
    const int warp_m = (wid >> 2) * 64;
    const int warp_n = (wid & 3) * 32;
    const int m0 = blockIdx.y * BM, n0 = blockIdx.x * BN;

    const float* A = q + h * SS * SS;    // Q_h, lda = SS
    const float* Vb = g_V + h * PP;

    float acc[4][4][4] = {};

    for (int k0 = 0; k0 < SS; k0 += BK) {
        #pragma unroll
        for (int i = 0; i < 4; i++) {
            int f4 = tid + i * 256;
            int m = f4 >> 3, kc = (f4 & 7) * 4;
            float4 v = *(const float4*)&A[(m0 + m) * SS + k0 + kc];
            uint32_t* d = &As[m * LDA + kc];
            d[0] = f2tf32(v.x); d[1] = f2tf32(v.y);
            d[2] = f2tf32(v.z); d[3] = f2tf32(v.w);
        }
        #pragma unroll
        for (int i = 0; i < 4; i++) {
            int f4 = tid + i * 256;
            int k = f4 >> 5, nc = (f4 & 31) * 4;
            int n = n0 + nc;
            float4 v = *(const float4*)&Vb[(((n >> 6) * SS) + k0 + k) * EE + (n & 63)];
            uint32_t* d = &Bs[k * LDB + nc];
            d[0] = f2tf32(v.x); d[1] = f2tf32(v.y);
            d[2] = f2tf32(v.z); d[3] = f2tf32(v.w);
        }
        __syncthreads();

        #pragma unroll
        for (int ks = 0; ks < BK / 8; ks++) {
            uint32_t af[4][4], bf[4][2];
            #pragma unroll
            for (int mt = 0; mt < 4; mt++) {
                int r = warp_m + mt * 16 + gid;
                int c = ks * 8 + tig;
                af[mt][0] = As[r * LDA + c];
                af[mt][1] = As[(r + 8) * LDA + c];
                af[mt][2] = As[r * LDA + c + 4];
                af[mt][3] = As[(r + 8) * LDA + c + 4];
            }
            #pragma unroll
            for (int nt = 0; nt < 4; nt++) {
                int k = ks * 8 + tig;
                int n = warp_n + nt * 8 + gid;
                bf[nt][0] = Bs[k * LDB + n];
                bf[nt][1] = Bs[(k + 4) * LDB + n];
            }
            #pragma unroll
            for (int mt = 0; mt < 4; mt++)
                #pragma unroll
                for (int nt = 0; nt < 4; nt++)
                    mma_tf32(acc[mt][nt], af[mt], bf[nt]);
        }
        __syncthreads();
    }

    float* QVb = g_QV + h * PP;
    #pragma unroll
    for (int mt = 0; mt < 4; mt++) {
        int r = m0 + warp_m + mt * 16 + gid;
        #pragma unroll
        for (int nt = 0; nt < 4; nt++) {
            int n = n0 + warp_n + nt * 8 + tig * 2;
            int b_ = n >> 6, p = n & 63;
            *(float2*)&QVb[(b_ * SS + r) * EE + p] =
                make_float2(acc[mt][nt][0], acc[mt][nt][1]);
            *(float2*)&QVb[(b_ * SS + r + 8) * EE + p] =
                make_float2(acc[mt][nt][2], acc[mt][nt][3]);
        }
    }
}

// ---------------------------------------------------------------------------
// Kernel 3: causal masked softmax attention, flash-style, max-free (scalar)
// score[i,j] = K[i].QV[j]/sqrt(E), j<=i; attn = P/l @ V -> g_At [b][s][h][p]
// ---------------------------------------------------------------------------
#define LDK 68
__global__ __launch_bounds__(256) void attn_kernel()
{
    extern __shared__ float sm[];
    float* ks = sm;                // 64*68
    float* qs = sm + 64 * LDK;     // 64*68, reused as P tile
    float* vs = sm + 2 * 64 * LDK; // 64*64

    const int it = blockIdx.x, h = blockIdx.y, b = blockIdx.z;
    const int i0 = it * 64;
    const int tid = threadIdx.x;
    const int tx = tid & 15, ty = tid >> 4;
    const int ty4 = ty * 4, tx4 = tx * 4;
    const float scale = 0.03608439182435161f;  // 1/sqrt(768)

    const float* Kb  = g_K  + b * SS * EE + h * PP;
    const float* QVb = g_QV + b * SS * EE + h * PP;
    const float* Vb  = g_V  + b * SS * EE + h * PP;

    #pragma unroll
    for (int t = 0; t < 16; t++) {
        int idx = tid + t * 256;
        int r = idx >> 6, p = idx & 63;
        ks[r * LDK + p] = Kb[(i0 + r) * EE + p];
    }

    float O[4][4] = {};
    float l[4] = {};

    for (int jt = 0; jt <= it; jt++) {
        const int j0 = jt * 64;
        #pragma unroll
        for (int t = 0; t < 16; t++) {
            int idx = tid + t * 256;
            int r = idx >> 6, p = idx & 63;
            qs[r * LDK + p] = QVb[(j0 + r) * EE + p];
            vs[r * 64  + p] = Vb [(j0 + r) * EE + p];
        }
        __syncthreads();

        float Sv[4][4] = {};
        #pragma unroll 4
        for (int p = 0; p < 64; p += 4) {
            float4 ka[4], qa[4];
            #pragma unroll
            for (int r = 0; r < 4; r++) ka[r] = *(const float4*)&ks[(ty4 + r) * LDK + p];
            #pragma unroll
            for (int c = 0; c < 4; c++) qa[c] = *(const float4*)&qs[(tx4 + c) * LDK + p];
            #pragma unroll
            for (int r = 0; r < 4; r++)
                #pragma unroll
                for (int c = 0; c < 4; c++)
                    Sv[r][c] += ka[r].x * qa[c].x + ka[r].y * qa[c].y +
                                ka[r].z * qa[c].z + ka[r].w * qa[c].w;
        }
        __syncthreads();

        #pragma unroll
        for (int r = 0; r < 4; r++) {
            int i = i0 + ty4 + r;
            #pragma unroll
            for (int c = 0; c < 4; c++) {
                int j = j0 + tx4 + c;
                float e = (j <= i) ? __expf(Sv[r][c] * scale) : 0.0f;
                l[r] += e;
                qs[(ty4 + r) * LDK + (tx4 + c)] = e;
            }
        }
        __syncthreads();

        #pragma unroll 4
        for (int j = 0; j < 64; j += 4) {
            float4 pa[4], va[4];
            #pragma unroll
            for (int r = 0; r < 4; r++) pa[r] = *(const float4*)&qs[(ty4 + r) * LDK + j];
            #pragma unroll
            for (int jj = 0; jj < 4; jj++) va[jj] = *(const float4*)&vs[(j + jj) * 64 + tx4];
            #pragma unroll
            for (int r = 0; r < 4; r++) {
                float pv[4] = {pa[r].x, pa[r].y, pa[r].z, pa[r].w};
                #pragma unroll
                for (int jj = 0; jj < 4; jj++) {
                    O[r][0] = fmaf(pv[jj], va[jj].x, O[r][0]);
                    O[r][1] = fmaf(pv[jj], va[jj].y, O[r][1]);
                    O[r][2] = fmaf(pv[jj], va[jj].z, O[r][2]);
                    O[r][3] = fmaf(pv[jj], va[jj].w, O[r][3]);
                }
            }
        }
        __syncthreads();
    }

    #pragma unroll
    for (int r = 0; r < 4; r++) {
        #pragma unroll
        for (int m = 8; m >= 1; m >>= 1)
            l[r] += __shfl_xor_sync(0xffffffffu, l[r], m, 16);
    }

    #pragma unroll
    for (int r = 0; r < 4; r++) {
        int i = i0 + ty4 + r;
        float inv = 1.0f / l[r];
        *(float4*)&g_At[(b * SS + i) * EE + h * PP + tx4] =
            make_float4(O[r][0] * inv, O[r][1] * inv, O[r][2] * inv, O[r][3] * inv);
    }
}

// ---------------------------------------------------------------------------
extern "C" void kernel_launch(void* const* d_in, const int* in_sizes, int n_in,
                              void* d_out, int out_size)
{
    const float* x    = (const float*)d_in[0];  // (B,1,S,E)
    const float* wk   = (const float*)d_in[1];  // (H,E,P)
    const float* wv   = (const float*)d_in[2];  // (H,E,P)
    const float* q    = (const float*)d_in[3];  // (H,S,S)
    const float* lift = (const float*)d_in[4];  // (1,H*P,E)
    float* out = (float*)d_out;                 // (B,S,E)

    cudaFuncSetAttribute(attn_kernel,
                         cudaFuncAttributeMaxDynamicSharedMemorySize, 64 * 1024);

    float* gK;  cudaGetSymbolAddress((void**)&gK,  g_K);
    float* gV;  cudaGetSymbolAddress((void**)&gV,  g_V);
    float* gAt; cudaGetSymbolAddress((void**)&gAt, g_At);

    const int M = BB * SS;  // 8192

    // K = X @ Wk_packed, V = X @ Wv_packed  (head-packed B)
    dim3 gp(EE / BN, M / BM);
    gemm_tf32_kernel<1><<<gp, 256>>>(x, wk, gK, M, EE, EE, EE, 0, EE);
    gemm_tf32_kernel<1><<<gp, 256>>>(x, wv, gV, M, EE, EE, EE, 0, EE);

    // QV = Q_h @ Vcat per head
    dim3 gq((BB * PP) / BN, SS / BM, HH);
    qv_tf32_kernel<<<gq, 256>>>(q);

    // causal attention (scalar flash)
    dim3 ga(SS / 64, HH, BB);
    attn_kernel<<<ga, 256, 51200>>>();

    // out = attn @ lifting  (plain B)
    gemm_tf32_kernel<0><<<gp, 256>>>(gAt, lift, out, M, EE, EE, EE, EE, EE);
}

// round 4
// speedup vs baseline: 4.3534x; 3.4265x over previous
#include <cuda_runtime.h>
#include <cuda_bf16.h>
#include <cstdint>

#define BB 8
#define SS 1024
#define EE 768
#define HH 12
#define PP 64

// ---------------------------------------------------------------------------
// Scratch (__device__ globals; allocation-free rule)
// ---------------------------------------------------------------------------
__device__ float g_K  [BB*SS*EE];   // tf32-rounded, [b][s][h][p]
__device__ float g_V  [BB*SS*EE];   // tf32-rounded
__device__ float g_QV [BB*SS*EE];   // tf32-rounded
__device__ float g_At [BB*SS*EE];   // tf32-rounded
__device__ float g_Xt [BB*SS*EE];   // tf32-rounded copy of x
__device__ float g_Qt [HH*SS*SS];   // tf32-rounded copy of q_heads
__device__ float g_Wkt[HH*EE*PP];
__device__ float g_Wvt[HH*EE*PP];
__device__ float g_Ltt[EE*EE];

// ---------------------------------------------------------------------------
// helpers
// ---------------------------------------------------------------------------
__device__ __forceinline__ uint32_t f2tf32(float f) {
    uint32_t u;
    asm("cvt.rna.tf32.f32 %0, %1;" : "=r"(u) : "f"(f));
    return u;
}
__device__ __forceinline__ float rnd_tf32(float f) {
    return __uint_as_float(f2tf32(f));
}
__device__ __forceinline__ void mma_tf32(float c[4], const uint32_t a[4],
                                         const uint32_t b[2]) {
    asm volatile(
        "mma.sync.aligned.m16n8k8.row.col.f32.tf32.tf32.f32 "
        "{%0,%1,%2,%3}, {%4,%5,%6,%7}, {%8,%9}, {%0,%1,%2,%3};"
        : "+f"(c[0]), "+f"(c[1]), "+f"(c[2]), "+f"(c[3])
        : "r"(a[0]), "r"(a[1]), "r"(a[2]), "r"(a[3]), "r"(b[0]), "r"(b[1]));
}
__device__ __forceinline__ void cp_async16(void* sptr, const void* gptr) {
    uint32_t s = (uint32_t)__cvta_generic_to_shared(sptr);
    asm volatile("cp.async.cg.shared.global [%0], [%1], 16;\n"
                 :: "r"(s), "l"(gptr) : "memory");
}
#define CP_COMMIT() asm volatile("cp.async.commit_group;\n" ::: "memory")
#define CP_WAIT(n)  asm volatile("cp.async.wait_group %0;\n" :: "n"(n) : "memory")

// ---------------------------------------------------------------------------
// Prepass: elementwise tf32 rounding
// ---------------------------------------------------------------------------
__global__ void round_kernel(const float* __restrict__ in,
                             float* __restrict__ out, int n4)
{
    int i = blockIdx.x * blockDim.x + threadIdx.x;
    if (i < n4) {
        float4 v = ((const float4*)in)[i];
        v.x = rnd_tf32(v.x); v.y = rnd_tf32(v.y);
        v.z = rnd_tf32(v.z); v.w = rnd_tf32(v.w);
        ((float4*)out)[i] = v;
    }
}

// ---------------------------------------------------------------------------
// TF32 GEMM, 2-stage cp.async double buffered.
// C(MxN) = A(MxK) @ B(KxN).   BMODE 0: plain row-major B (ldb).
// BMODE 1: head-packed B: B[k][n] = w[(n>>6)*K*64 + k*64 + (n&63)].
// ROUND 1: round output to tf32 (feeds another mma stage).
// grid (N/128, M/128), 256 threads.
// ---------------------------------------------------------------------------
#define BM 128
#define BN 128
#define BK 32
#define LDA 36
#define LDB 136
#define GEMM_SMEM ((2*BM*LDA + 2*BK*LDB) * 4)

template <int BMODE, int ROUND>
__global__ __launch_bounds__(256) void gemm_tf32_kernel(
    const float* __restrict__ A, const float* __restrict__ Bm,
    float* __restrict__ C, int K, int lda, int ldb, int ldc)
{
    extern __shared__ float smx[];
    float* As = smx;                    // 2 x 128 x 36
    float* Bs = smx + 2 * BM * LDA;     // 2 x 32 x 136

    const int tid = threadIdx.x;
    const int wid = tid >> 5, lane = tid & 31;
    const int gid = lane >> 2, tig = lane & 3;
    const int warp_m = (wid >> 2) * 64;
    const int warp_n = (wid & 3) * 32;
    const int m0 = blockIdx.y * BM, n0 = blockIdx.x * BN;

    float acc[4][4][4] = {};

    auto load_tile = [&](int k0, int stage) {
        float* Ad = As + stage * (BM * LDA);
        float* Bd = Bs + stage * (BK * LDB);
        #pragma unroll
        for (int i = 0; i < 4; i++) {
            int f4 = tid + i * 256;
            int m = f4 >> 3, kc = (f4 & 7) * 4;
            cp_async16(&Ad[m * LDA + kc], &A[(size_t)(m0 + m) * lda + k0 + kc]);
        }
        #pragma unroll
        for (int i = 0; i < 4; i++) {
            int f4 = tid + i * 256;
            int k = f4 >> 5, nc = (f4 & 31) * 4;
            int n = n0 + nc;
            const float* src = (BMODE == 0)
                ? &Bm[(size_t)(k0 + k) * ldb + n]
                : &Bm[(size_t)(n >> 6) * (K * 64) + (k0 + k) * 64 + (n & 63)];
            cp_async16(&Bd[k * LDB + nc], src);
        }
    };

    load_tile(0, 0);
    CP_COMMIT();

    const int ntiles = K / BK;
    for (int kt = 0; kt < ntiles; kt++) {
        if (kt + 1 < ntiles) {
            load_tile((kt + 1) * BK, (kt + 1) & 1);
            CP_COMMIT();
            CP_WAIT(1);
        } else {
            CP_WAIT(0);
        }
        __syncthreads();

        const float* Ad = As + (kt & 1) * (BM * LDA);
        const float* Bd = Bs + (kt & 1) * (BK * LDB);
        #pragma unroll
        for (int ks = 0; ks < BK / 8; ks++) {
            const int kk = ks * 8;
            uint32_t af[4][4], bf[4][2];
            #pragma unroll
            for (int mt = 0; mt < 4; mt++) {
                int r = warp_m + mt * 16 + gid;
                af[mt][0] = __float_as_uint(Ad[r * LDA + kk + tig]);
                af[mt][1] = __float_as_uint(Ad[(r + 8) * LDA + kk + tig]);
                af[mt][2] = __float_as_uint(Ad[r * LDA + kk + tig + 4]);
                af[mt][3] = __float_as_uint(Ad[(r + 8) * LDA + kk + tig + 4]);
            }
            #pragma unroll
            for (int nt = 0; nt < 4; nt++) {
                int n = warp_n + nt * 8 + gid;
                bf[nt][0] = __float_as_uint(Bd[(kk + tig) * LDB + n]);
                bf[nt][1] = __float_as_uint(Bd[(kk + tig + 4) * LDB + n]);
            }
            #pragma unroll
            for (int mt = 0; mt < 4; mt++)
                #pragma unroll
                for (int nt = 0; nt < 4; nt++)
                    mma_tf32(acc[mt][nt], af[mt], bf[nt]);
        }
        __syncthreads();
    }

    #pragma unroll
    for (int mt = 0; mt < 4; mt++) {
        int r = m0 + warp_m + mt * 16 + gid;
        #pragma unroll
        for (int nt = 0; nt < 4; nt++) {
            int c = n0 + warp_n + nt * 8 + tig * 2;
            float o0 = acc[mt][nt][0], o1 = acc[mt][nt][1];
            float o2 = acc[mt][nt][2], o3 = acc[mt][nt][3];
            if (ROUND) {
                o0 = rnd_tf32(o0); o1 = rnd_tf32(o1);
                o2 = rnd_tf32(o2); o3 = rnd_tf32(o3);
            }
            *(float2*)&C[(size_t)r * ldc + c] = make_float2(o0, o1);
            *(float2*)&C[(size_t)(r + 8) * ldc + c] = make_float2(o2, o3);
        }
    }
}

// ---------------------------------------------------------------------------
// QV GEMM per head: QVcat(1024 x 512) = Q_h(1024x1024) @ Vcat(1024x512)
//   Vcat[k][n] = g_V[((n>>6)*SS + k)*EE + h*PP + (n&63)]
// grid (4, 8, 12), 256 threads.
// ---------------------------------------------------------------------------
__global__ __launch_bounds__(256) void qv_tf32_kernel()
{
    extern __shared__ float smx[];
    float* As = smx;
    float* Bs = smx + 2 * BM * LDA;

    const int h = blockIdx.z;
    const int tid = threadIdx.x;
    const int wid = tid >> 5, lane = tid & 31;
    const int gid = lane >> 2, tig = lane & 3;
    const int warp_m = (wid >> 2) * 64;
    const int warp_n = (wid & 3) * 32;
    const int m0 = blockIdx.y * BM, n0 = blockIdx.x * BN;

    const float* A  = g_Qt + (size_t)h * SS * SS;
    const float* Vb = g_V + h * PP;

    float acc[4][4][4] = {};

    auto load_tile = [&](int k0, int stage) {
        float* Ad = As + stage * (BM * LDA);
        float* Bd = Bs + stage * (BK * LDB);
        #pragma unroll
        for (int i = 0; i < 4; i++) {
            int f4 = tid + i * 256;
            int m = f4 >> 3, kc = (f4 & 7) * 4;
            cp_async16(&Ad[m * LDA + kc], &A[(size_t)(m0 + m) * SS + k0 + kc]);
        }
        #pragma unroll
        for (int i = 0; i < 4; i++) {
            int f4 = tid + i * 256;
            int k = f4 >> 5, nc = (f4 & 31) * 4;
            int n = n0 + nc;
            cp_async16(&Bd[k * LDB + nc],
                       &Vb[(size_t)((n >> 6) * SS + k0 + k) * EE + (n & 63)]);
        }
    };

    load_tile(0, 0);
    CP_COMMIT();

    const int ntiles = SS / BK;
    for (int kt = 0; kt < ntiles; kt++) {
        if (kt + 1 < ntiles) {
            load_tile((kt + 1) * BK, (kt + 1) & 1);
            CP_COMMIT();
            CP_WAIT(1);
        } else {
            CP_WAIT(0);
        }
        __syncthreads();

        const float* Ad = As + (kt & 1) * (BM * LDA);
        const float* Bd = Bs + (kt & 1) * (BK * LDB);
        #pragma unroll
        for (int ks = 0; ks < BK / 8; ks++) {
            const int kk = ks * 8;
            uint32_t af[4][4], bf[4][2];
            #pragma unroll
            for (int mt = 0; mt < 4; mt++) {
                int r = warp_m + mt * 16 + gid;
                af[mt][0] = __float_as_uint(Ad[r * LDA + kk + tig]);
                af[mt][1] = __float_as_uint(Ad[(r + 8) * LDA + kk + tig]);
                af[mt][2] = __float_as_uint(Ad[r * LDA + kk + tig + 4]);
                af[mt][3] = __float_as_uint(Ad[(r + 8) * LDA + kk + tig + 4]);
            }
            #pragma unroll
            for (int nt = 0; nt < 4; nt++) {
                int n = warp_n + nt * 8 + gid;
                bf[nt][0] = __float_as_uint(Bd[(kk + tig) * LDB + n]);
                bf[nt][1] = __float_as_uint(Bd[(kk + tig + 4) * LDB + n]);
            }
            #pragma unroll
            for (int mt = 0; mt < 4; mt++)
                #pragma unroll
                for (int nt = 0; nt < 4; nt++)
                    mma_tf32(acc[mt][nt], af[mt], bf[nt]);
        }
        __syncthreads();
    }

    float* QVb = g_QV + h * PP;
    #pragma unroll
    for (int mt = 0; mt < 4; mt++) {
        int r = m0 + warp_m + mt * 16 + gid;
        #pragma unroll
        for (int nt = 0; nt < 4; nt++) {
            int n = n0 + warp_n + nt * 8 + tig * 2;
            int b_ = n >> 6, p = n & 63;
            *(float2*)&QVb[(size_t)(b_ * SS + r) * EE + p] =
                make_float2(rnd_tf32(acc[mt][nt][0]), rnd_tf32(acc[mt][nt][1]));
            *(float2*)&QVb[(size_t)(b_ * SS + r + 8) * EE + p] =
                make_float2(rnd_tf32(acc[mt][nt][2]), rnd_tf32(acc[mt][nt][3]));
        }
    }
}

// ---------------------------------------------------------------------------
// Tensor-core causal attention (max-free flash):
//   S[i][j] = K[i]·QV[j], P = exp(S*scale) masked j<=i, l = rowsum(P),
//   O = (P/l) @ V  ->  g_At [b][s][h][p] (tf32-rounded)
// Block: 256 threads, 128 rows; j-tiles of 64.
// ---------------------------------------------------------------------------
#define ALDK 68
#define ALDV 72
#define ATT_SMEM ((128*ALDK + 64*ALDK + 64*ALDV + 128*ALDK + 128*4) * 4)

__global__ __launch_bounds__(256) void attn_mma_kernel()
{
    extern __shared__ float sm[];
    float* ks  = sm;                       // 128 x 68
    float* qs  = ks + 128 * ALDK;          // 64 x 68
    float* vs  = qs + 64 * ALDK;           // 64 x 72
    float* ps  = vs + 64 * ALDV;           // 128 x 68
    float* lsm = ps + 128 * ALDK;          // 128 x 4

    const int it = 7 - (int)blockIdx.x;    // heavy blocks first
    const int h = blockIdx.y, b = blockIdx.z;
    const int i0 = it * 128;
    const int tid = threadIdx.x;
    const int wid = tid >> 5, lane = tid & 31;
    const int gid = lane >> 2, tig = lane & 3;
    const int wm = wid >> 2, wn = wid & 3;
    const int rbase = wm * 64;
    const int cbase = wn * 16;
    const float scale = 0.03608439182435161f;  // 1/sqrt(768)

    const float* Kb  = g_K  + (size_t)b * SS * EE + h * PP;
    const float* QVb = g_QV + (size_t)b * SS * EE + h * PP;
    const float* Vb  = g_V  + (size_t)b * SS * EE + h * PP;

    // persistent K tile (128 x 64)
    #pragma unroll
    for (int t = 0; t < 8; t++) {
        int idx = tid + t * 256;
        int r = idx >> 4, c4 = (idx & 15) * 4;
        *(float4*)&ks[r * ALDK + c4] = *(const float4*)&Kb[(size_t)(i0 + r) * EE + c4];
    }

    float Oa[4][2][4] = {};
    float lacc[4][2] = {};

    const int njt = 2 * it + 2;
    for (int jt = 0; jt < njt; jt++) {
        const int j0 = jt * 64;
        #pragma unroll
        for (int t = 0; t < 4; t++) {
            int idx = tid + t * 256;
            int r = idx >> 4, c4 = (idx & 15) * 4;
            *(float4*)&qs[r * ALDK + c4] = *(const float4*)&QVb[(size_t)(j0 + r) * EE + c4];
            *(float4*)&vs[r * ALDV + c4] = *(const float4*)&Vb[(size_t)(j0 + r) * EE + c4];
        }
        __syncthreads();

        // ---- S = K @ QV^T  (M=128 i, N=64 j, K=64 p)
        float Sa[4][2][4] = {};
        #pragma unroll
        for (int kss = 0; kss < 8; kss++) {
            const int kk = kss * 8;
            uint32_t af[4][4], bf[2][2];
            #pragma unroll
            for (int mt = 0; mt < 4; mt++) {
                int r = rbase + mt * 16 + gid;
                af[mt][0] = __float_as_uint(ks[r * ALDK + kk + tig]);
                af[mt][1] = __float_as_uint(ks[(r + 8) * ALDK + kk + tig]);
                af[mt][2] = __float_as_uint(ks[r * ALDK + kk + tig + 4]);
                af[mt][3] = __float_as_uint(ks[(r + 8) * ALDK + kk + tig + 4]);
            }
            #pragma unroll
            for (int nt = 0; nt < 2; nt++) {
                int n = cbase + nt * 8 + gid;
                bf[nt][0] = __float_as_uint(qs[n * ALDK + kk + tig]);
                bf[nt][1] = __float_as_uint(qs[n * ALDK + kk + tig + 4]);
            }
            #pragma unroll
            for (int mt = 0; mt < 4; mt++)
                #pragma unroll
                for (int nt = 0; nt < 2; nt++)
                    mma_tf32(Sa[mt][nt], af[mt], bf[nt]);
        }

        // ---- mask + exp, write P tile (tf32), accumulate row sums
        const bool need_mask = (jt >= 2 * it);
        #pragma unroll
        for (int mt = 0; mt < 4; mt++) {
            #pragma unroll
            for (int nt = 0; nt < 2; nt++) {
                int rr0 = rbase + mt * 16 + gid;
                int cc = cbase + nt * 8 + 2 * tig;
                int iglob0 = i0 + rr0, iglob1 = iglob0 + 8;
                int jg = j0 + cc;
                float e0 = __expf(Sa[mt][nt][0] * scale);
                float e1 = __expf(Sa[mt][nt][1] * scale);
                float e2 = __expf(Sa[mt][nt][2] * scale);
                float e3 = __expf(Sa[mt][nt][3] * scale);
                if (need_mask) {
                    if (jg     > iglob0) e0 = 0.0f;
                    if (jg + 1 > iglob0) e1 = 0.0f;
                    if (jg     > iglob1) e2 = 0.0f;
                    if (jg + 1 > iglob1) e3 = 0.0f;
                }
                lacc[mt][0] += e0 + e1;
                lacc[mt][1] += e2 + e3;
                *(float2*)&ps[rr0 * ALDK + cc] =
                    make_float2(rnd_tf32(e0), rnd_tf32(e1));
                *(float2*)&ps[(rr0 + 8) * ALDK + cc] =
                    make_float2(rnd_tf32(e2), rnd_tf32(e3));
            }
        }
        __syncthreads();

        // ---- O += P @ V  (M=128 i, N=64 p, K=64 j)
        #pragma unroll
        for (int kss = 0; kss < 8; kss++) {
            const int kk = kss * 8;
            uint32_t af[4][4], bf[2][2];
            #pragma unroll
            for (int mt = 0; mt < 4; mt++) {
                int r = rbase + mt * 16 + gid;
                af[mt][0] = __float_as_uint(ps[r * ALDK + kk + tig]);
                af[mt][1] = __float_as_uint(ps[(r + 8) * ALDK + kk + tig]);
                af[mt][2] = __float_as_uint(ps[r * ALDK + kk + tig + 4]);
                af[mt][3] = __float_as_uint(ps[(r + 8) * ALDK + kk + tig + 4]);
            }
            #pragma unroll
            for (int nt = 0; nt < 2; nt++) {
                int n = cbase + nt * 8 + gid;
                bf[nt][0] = __float_as_uint(vs[(kk + tig) * ALDV + n]);
                bf[nt][1] = __float_as_uint(vs[(kk + tig + 4) * ALDV + n]);
            }
            #pragma unroll
            for (int mt = 0; mt < 4; mt++)
                #pragma unroll
                for (int nt = 0; nt < 2; nt++)
                    mma_tf32(Oa[mt][nt], af[mt], bf[nt]);
        }
        __syncthreads();
    }

    // ---- reduce l: quad shuffle (over tig), then across the 4 wn warps
    #pragma unroll
    for (int mt = 0; mt < 4; mt++) {
        #pragma unroll
        for (int rr = 0; rr < 2; rr++) {
            float v = lacc[mt][rr];
            v += __shfl_xor_sync(0xffffffffu, v, 1);
            v += __shfl_xor_sync(0xffffffffu, v, 2);
            lacc[mt][rr] = v;
        }
    }
    if (tig == 0) {
        #pragma unroll
        for (int mt = 0; mt < 4; mt++) {
            int r = rbase + mt * 16 + gid;
            lsm[r * 4 + wn] = lacc[mt][0];
            lsm[(r + 8) * 4 + wn] = lacc[mt][1];
        }
    }
    __syncthreads();

    float* Ab = g_At + (size_t)b * SS * EE + h * PP;
    #pragma unroll
    for (int mt = 0; mt < 4; mt++) {
        int r = rbase + mt * 16 + gid;
        float inv0 = 1.0f / (lsm[r * 4] + lsm[r * 4 + 1] + lsm[r * 4 + 2] + lsm[r * 4 + 3]);
        int r8 = r + 8;
        float inv1 = 1.0f / (lsm[r8 * 4] + lsm[r8 * 4 + 1] + lsm[r8 * 4 + 2] + lsm[r8 * 4 + 3]);
        #pragma unroll
        for (int nt = 0; nt < 2; nt++) {
            int c = cbase + nt * 8 + 2 * tig;
            *(float2*)&Ab[(size_t)(i0 + r) * EE + c] =
                make_float2(rnd_tf32(Oa[mt][nt][0] * inv0), rnd_tf32(Oa[mt][nt][1] * inv0));
            *(float2*)&Ab[(size_t)(i0 + r8) * EE + c] =
                make_float2(rnd_tf32(Oa[mt][nt][2] * inv1), rnd_tf32(Oa[mt][nt][3] * inv1));
        }
    }
}

// ---------------------------------------------------------------------------
extern "C" void kernel_launch(void* const* d_in, const int* in_sizes, int n_in,
                              void* d_out, int out_size)
{
    const float* x    = (const float*)d_in[0];
    const float* wk   = (const float*)d_in[1];
    const float* wv   = (const float*)d_in[2];
    const float* q    = (const float*)d_in[3];
    const float* lift = (const float*)d_in[4];
    float* out = (float*)d_out;

    static bool attr_done = false;
    if (!attr_done) {
        cudaFuncSetAttribute(gemm_tf32_kernel<0,0>,
            cudaFuncAttributeMaxDynamicSharedMemorySize, GEMM_SMEM);
        cudaFuncSetAttribute(gemm_tf32_kernel<1,1>,
            cudaFuncAttributeMaxDynamicSharedMemorySize, GEMM_SMEM);
        cudaFuncSetAttribute(qv_tf32_kernel,
            cudaFuncAttributeMaxDynamicSharedMemorySize, GEMM_SMEM);
        cudaFuncSetAttribute(attn_mma_kernel,
            cudaFuncAttributeMaxDynamicSharedMemorySize, ATT_SMEM);
        attr_done = true;
    }

    float *gK, *gV, *gAt, *gXt, *gQt, *gWkt, *gWvt, *gLtt;
    cudaGetSymbolAddress((void**)&gK,  g_K);
    cudaGetSymbolAddress((void**)&gV,  g_V);
    cudaGetSymbolAddress((void**)&gAt, g_At);
    cudaGetSymbolAddress((void**)&gXt, g_Xt);
    cudaGetSymbolAddress((void**)&gQt, g_Qt);
    cudaGetSymbolAddress((void**)&gWkt, g_Wkt);
    cudaGetSymbolAddress((void**)&gWvt, g_Wvt);
    cudaGetSymbolAddress((void**)&gLtt, g_Ltt);

    // --- prepass: tf32-round all mma inputs
    auto launch_round = [&](const float* src, float* dst, int n) {
        int n4 = n / 4;
        round_kernel<<<(n4 + 255) / 256, 256>>>(src, dst, n4);
    };
    launch_round(x,    gXt,  BB * SS * EE);
    launch_round(q,    gQt,  HH * SS * SS);
    launch_round(wk,   gWkt, HH * EE * PP);
    launch_round(wv,   gWvt, HH * EE * PP);
    launch_round(lift, gLtt, EE * EE);

    const int M = BB * SS;

    // --- K/V projections (head-packed B), round outputs
    dim3 gp(EE / BN, M / BM);
    gemm_tf32_kernel<1,1><<<gp, 256, GEMM_SMEM>>>(gXt, gWkt, gK, EE, EE, 0, EE);
    gemm_tf32_kernel<1,1><<<gp, 256, GEMM_SMEM>>>(gXt, gWvt, gV, EE, EE, 0, EE);

    // --- QV = Q_h @ Vcat per head
    dim3 gq((BB * PP) / BN, SS / BM, HH);
    qv_tf32_kernel<<<gq, 256, GEMM_SMEM>>>();

    // --- causal attention (tensor core)
    dim3 ga(SS / 128, HH, BB);
    attn_mma_kernel<<<ga, 256, ATT_SMEM>>>();

    // --- out = attn @ lifting (fp32 output, no rounding)
    gemm_tf32_kernel<0,0><<<gp, 256, GEMM_SMEM>>>(gAt, gLtt, out, EE, EE, EE, EE);
}

// round 7
// speedup vs baseline: 4.6754x; 1.0740x over previous
#include <cuda_runtime.h>
#include <cuda_bf16.h>
#include <cstdint>

#define BB 8
#define SS 1024
#define EE 768
#define HH 12
#define PP 64

// ---------------------------------------------------------------------------
// Scratch (__device__ globals; allocation-free rule)
// ---------------------------------------------------------------------------
__device__ float g_K  [BB*SS*EE];   // tf32-rounded, [b][s][h][p]
__device__ float g_V  [BB*SS*EE];   // tf32-rounded
__device__ float g_QV [BB*SS*EE];   // tf32-rounded
__device__ float g_At [BB*SS*EE];   // tf32-rounded
__device__ float g_Xt [BB*SS*EE];   // tf32-rounded copy of x
__device__ float g_Qt [HH*SS*SS];   // tf32-rounded copy of q_heads
__device__ float g_Wkt[HH*EE*PP];
__device__ float g_Wvt[HH*EE*PP];
__device__ float g_Ltt[EE*EE];

// ---------------------------------------------------------------------------
// helpers
// ---------------------------------------------------------------------------
__device__ __forceinline__ uint32_t f2tf32(float f) {
    uint32_t u;
    asm("cvt.rna.tf32.f32 %0, %1;" : "=r"(u) : "f"(f));
    return u;
}
__device__ __forceinline__ float rnd_tf32(float f) {
    return __uint_as_float(f2tf32(f));
}
__device__ __forceinline__ void mma_tf32(float c[4], const uint32_t a[4],
                                         const uint32_t b[2]) {
    asm volatile(
        "mma.sync.aligned.m16n8k8.row.col.f32.tf32.tf32.f32 "
        "{%0,%1,%2,%3}, {%4,%5,%6,%7}, {%8,%9}, {%0,%1,%2,%3};"
        : "+f"(c[0]), "+f"(c[1]), "+f"(c[2]), "+f"(c[3])
        : "r"(a[0]), "r"(a[1]), "r"(a[2]), "r"(a[3]), "r"(b[0]), "r"(b[1]));
}
__device__ __forceinline__ void cp_async16(void* sptr, const void* gptr) {
    uint32_t s = (uint32_t)__cvta_generic_to_shared(sptr);
    asm volatile("cp.async.cg.shared.global [%0], [%1], 16;\n"
                 :: "r"(s), "l"(gptr) : "memory");
}
#define CP_COMMIT() asm volatile("cp.async.commit_group;\n" ::: "memory")
#define CP_WAIT(n)  asm volatile("cp.async.wait_group %0;\n" :: "n"(n) : "memory")

// ---------------------------------------------------------------------------
// Prepass: elementwise tf32 rounding
// ---------------------------------------------------------------------------
__global__ void round_kernel(const float* __restrict__ in,
                             float* __restrict__ out, int n4)
{
    int i = blockIdx.x * blockDim.x + threadIdx.x;
    if (i < n4) {
        float4 v = ((const float4*)in)[i];
        v.x = rnd_tf32(v.x); v.y = rnd_tf32(v.y);
        v.z = rnd_tf32(v.z); v.w = rnd_tf32(v.w);
        ((float4*)out)[i] = v;
    }
}

// ---------------------------------------------------------------------------
// TF32 GEMM, 3-stage cp.async pipeline, 1 __syncthreads per k-tile.
// C(MxN) = A(MxK) @ B(KxN).   BMODE 0: plain row-major B (ldb).
// BMODE 1: head-packed B: B[k][n] = w[(n>>6)*K*64 + k*64 + (n&63)].
// ROUND 1: round output to tf32 (feeds another mma stage).
// grid (N/128, M/128), 256 threads.
// ---------------------------------------------------------------------------
#define BM 128
#define BN 128
#define BK 32
#define LDA 36
#define LDB 136
#define STAGES 3
#define GEMM_SMEM ((STAGES*(BM*LDA + BK*LDB)) * 4)

template <int BMODE, int ROUND>
__global__ __launch_bounds__(256, 2) void gemm_tf32_kernel(
    const float* __restrict__ A, const float* __restrict__ Bm,
    float* __restrict__ C, int K, int lda, int ldb, int ldc)
{
    extern __shared__ float smx[];
    float* As = smx;                          // STAGES x 128 x 36
    float* Bs = smx + STAGES * BM * LDA;      // STAGES x 32 x 136

    const int tid = threadIdx.x;
    const int wid = tid >> 5, lane = tid & 31;
    const int gid = lane >> 2, tig = lane & 3;
    const int warp_m = (wid >> 2) * 64;
    const int warp_n = (wid & 3) * 32;
    const int m0 = blockIdx.y * BM, n0 = blockIdx.x * BN;

    float acc[4][4][4] = {};

    auto load_tile = [&](int k0, int stage) {
        float* Ad = As + stage * (BM * LDA);
        float* Bd = Bs + stage * (BK * LDB);
        #pragma unroll
        for (int i = 0; i < 4; i++) {
            int f4 = tid + i * 256;
            int m = f4 >> 3, kc = (f4 & 7) * 4;
            cp_async16(&Ad[m * LDA + kc], &A[(size_t)(m0 + m) * lda + k0 + kc]);
        }
        #pragma unroll
        for (int i = 0; i < 4; i++) {
            int f4 = tid + i * 256;
            int k = f4 >> 5, nc = (f4 & 31) * 4;
            int n = n0 + nc;
            const float* src = (BMODE == 0)
                ? &Bm[(size_t)(k0 + k) * ldb + n]
                : &Bm[(size_t)(n >> 6) * (K * 64) + (k0 + k) * 64 + (n & 63)];
            cp_async16(&Bd[k * LDB + nc], src);
        }
    };

    const int ntiles = K / BK;
    load_tile(0, 0); CP_COMMIT();
    load_tile(BK, 1); CP_COMMIT();

    for (int kt = 0; kt < ntiles; kt++) {
        CP_WAIT(1);
        __syncthreads();
        // prefetch kt+2 into the stage compute(kt-1) just released
        if (kt + 2 < ntiles) {
            int s = (kt + 2) % STAGES;
            load_tile((kt + 2) * BK, s);
        }
        CP_COMMIT();

        const float* Ad = As + (kt % STAGES) * (BM * LDA);
        const float* Bd = Bs + (kt % STAGES) * (BK * LDB);
        #pragma unroll
        for (int ks = 0; ks < BK / 8; ks++) {
            const int kk = ks * 8;
            uint32_t af[4][4], bf[4][2];
            #pragma unroll
            for (int mt = 0; mt < 4; mt++) {
                int r = warp_m + mt * 16 + gid;
                af[mt][0] = __float_as_uint(Ad[r * LDA + kk + tig]);
                af[mt][1] = __float_as_uint(Ad[(r + 8) * LDA + kk + tig]);
                af[mt][2] = __float_as_uint(Ad[r * LDA + kk + tig + 4]);
                af[mt][3] = __float_as_uint(Ad[(r + 8) * LDA + kk + tig + 4]);
            }
            #pragma unroll
            for (int nt = 0; nt < 4; nt++) {
                int n = warp_n + nt * 8 + gid;
                bf[nt][0] = __float_as_uint(Bd[(kk + tig) * LDB + n]);
                bf[nt][1] = __float_as_uint(Bd[(kk + tig + 4) * LDB + n]);
            }
            #pragma unroll
            for (int mt = 0; mt < 4; mt++)
                #pragma unroll
                for (int nt = 0; nt < 4; nt++)
                    mma_tf32(acc[mt][nt], af[mt], bf[nt]);
        }
    }

    __syncthreads();
    #pragma unroll
    for (int mt = 0; mt < 4; mt++) {
        int r = m0 + warp_m + mt * 16 + gid;
        #pragma unroll
        for (int nt = 0; nt < 4; nt++) {
            int c = n0 + warp_n + nt * 8 + tig * 2;
            float o0 = acc[mt][nt][0], o1 = acc[mt][nt][1];
            float o2 = acc[mt][nt][2], o3 = acc[mt][nt][3];
            if (ROUND) {
                o0 = rnd_tf32(o0); o1 = rnd_tf32(o1);
                o2 = rnd_tf32(o2); o3 = rnd_tf32(o3);
            }
            *(float2*)&C[(size_t)r * ldc + c] = make_float2(o0, o1);
            *(float2*)&C[(size_t)(r + 8) * ldc + c] = make_float2(o2, o3);
        }
    }
}

// ---------------------------------------------------------------------------
// QV GEMM per head, same 3-stage pipeline:
//   QVcat(1024 x 512) = Q_h(1024x1024) @ Vcat(1024x512)
//   Vcat[k][n] = g_V[((n>>6)*SS + k)*EE + h*PP + (n&63)]
// grid (4, 8, 12), 256 threads.
// ---------------------------------------------------------------------------
__global__ __launch_bounds__(256, 2) void qv_tf32_kernel()
{
    extern __shared__ float smx[];
    float* As = smx;
    float* Bs = smx + STAGES * BM * LDA;

    const int h = blockIdx.z;
    const int tid = threadIdx.x;
    const int wid = tid >> 5, lane = tid & 31;
    const int gid = lane >> 2, tig = lane & 3;
    const int warp_m = (wid >> 2) * 64;
    const int warp_n = (wid & 3) * 32;
    const int m0 = blockIdx.y * BM, n0 = blockIdx.x * BN;

    const float* A  = g_Qt + (size_t)h * SS * SS;
    const float* Vb = g_V + h * PP;

    float acc[4][4][4] = {};

    auto load_tile = [&](int k0, int stage) {
        float* Ad = As + stage * (BM * LDA);
        float* Bd = Bs + stage * (BK * LDB);
        #pragma unroll
        for (int i = 0; i < 4; i++) {
            int f4 = tid + i * 256;
            int m = f4 >> 3, kc = (f4 & 7) * 4;
            cp_async16(&Ad[m * LDA + kc], &A[(size_t)(m0 + m) * SS + k0 + kc]);
        }
        #pragma unroll
        for (int i = 0; i < 4; i++) {
            int f4 = tid + i * 256;
            int k = f4 >> 5, nc = (f4 & 31) * 4;
            int n = n0 + nc;
            cp_async16(&Bd[k * LDB + nc],
                       &Vb[(size_t)((n >> 6) * SS + k0 + k) * EE + (n & 63)]);
        }
    };

    const int ntiles = SS / BK;
    load_tile(0, 0); CP_COMMIT();
    load_tile(BK, 1); CP_COMMIT();

    for (int kt = 0; kt < ntiles; kt++) {
        CP_WAIT(1);
        __syncthreads();
        if (kt + 2 < ntiles) {
            int s = (kt + 2) % STAGES;
            load_tile((kt + 2) * BK, s);
        }
        CP_COMMIT();

        const float* Ad = As + (kt % STAGES) * (BM * LDA);
        const float* Bd = Bs + (kt % STAGES) * (BK * LDB);
        #pragma unroll
        for (int ks = 0; ks < BK / 8; ks++) {
            const int kk = ks * 8;
            uint32_t af[4][4], bf[4][2];
            #pragma unroll
            for (int mt = 0; mt < 4; mt++) {
                int r = warp_m + mt * 16 + gid;
                af[mt][0] = __float_as_uint(Ad[r * LDA + kk + tig]);
                af[mt][1] = __float_as_uint(Ad[(r + 8) * LDA + kk + tig]);
                af[mt][2] = __float_as_uint(Ad[r * LDA + kk + tig + 4]);
                af[mt][3] = __float_as_uint(Ad[(r + 8) * LDA + kk + tig + 4]);
            }
            #pragma unroll
            for (int nt = 0; nt < 4; nt++) {
                int n = warp_n + nt * 8 + gid;
                bf[nt][0] = __float_as_uint(Bd[(kk + tig) * LDB + n]);
                bf[nt][1] = __float_as_uint(Bd[(kk + tig + 4) * LDB + n]);
            }
            #pragma unroll
            for (int mt = 0; mt < 4; mt++)
                #pragma unroll
                for (int nt = 0; nt < 4; nt++)
                    mma_tf32(acc[mt][nt], af[mt], bf[nt]);
        }
    }

    __syncthreads();
    float* QVb = g_QV + h * PP;
    #pragma unroll
    for (int mt = 0; mt < 4; mt++) {
        int r = m0 + warp_m + mt * 16 + gid;
        #pragma unroll
        for (int nt = 0; nt < 4; nt++) {
            int n = n0 + warp_n + nt * 8 + tig * 2;
            int b_ = n >> 6, p = n & 63;
            *(float2*)&QVb[(size_t)(b_ * SS + r) * EE + p] =
                make_float2(rnd_tf32(acc[mt][nt][0]), rnd_tf32(acc[mt][nt][1]));
            *(float2*)&QVb[(size_t)(b_ * SS + r + 8) * EE + p] =
                make_float2(rnd_tf32(acc[mt][nt][2]), rnd_tf32(acc[mt][nt][3]));
        }
    }
}

// ---------------------------------------------------------------------------
// Tensor-core causal attention, cp.async prefetch, 2 barriers per j-tile.
// RACE-FIXED schedule: every SMEM write is issued only after the barrier
// that retires its readers.
//   top:  CP_WAIT(0)  (qs(jt) arrived — loaded under PV(jt-1))
//         __syncthreads (retires vs/ps readers of jt-1)
//         issue vs(jt)            — hidden under S-mma + exp
//         S-mma, exp→ps
//         CP_WAIT(0); __syncthreads
//         PV-mma
//         issue qs(jt+1)          — hidden under next-tile window
// ---------------------------------------------------------------------------
#define ALDK 68
#define ALDV 72
#define ATT_SMEM ((128*ALDK + 64*ALDK + 64*ALDV + 128*ALDK + 128*4) * 4)

__global__ __launch_bounds__(256, 2) void attn_mma_kernel()
{
    extern __shared__ float sm[];
    float* ks  = sm;                       // 128 x 68
    float* qs  = ks + 128 * ALDK;          // 64 x 68
    float* vs  = qs + 64 * ALDK;           // 64 x 72
    float* ps  = vs + 64 * ALDV;           // 128 x 68
    float* lsm = ps + 128 * ALDK;          // 128 x 4

    const int it = 7 - (int)blockIdx.x;    // heavy blocks first
    const int h = blockIdx.y, b = blockIdx.z;
    const int i0 = it * 128;
    const int tid = threadIdx.x;
    const int wid = tid >> 5, lane = tid & 31;
    const int gid = lane >> 2, tig = lane & 3;
    const int wm = wid >> 2, wn = wid & 3;
    const int rbase = wm * 64;
    const int cbase = wn * 16;
    const float scale = 0.03608439182435161f;  // 1/sqrt(768)

    const float* Kb  = g_K  + (size_t)b * SS * EE + h * PP;
    const float* QVb = g_QV + (size_t)b * SS * EE + h * PP;
    const float* Vb  = g_V  + (size_t)b * SS * EE + h * PP;

    // persistent K tile (128 x 64) via cp.async
    #pragma unroll
    for (int t = 0; t < 8; t++) {
        int idx = tid + t * 256;
        int r = idx >> 4, c4 = (idx & 15) * 4;
        cp_async16(&ks[r * ALDK + c4], &Kb[(size_t)(i0 + r) * EE + c4]);
    }
    CP_COMMIT();

    // prefetch qs(0)
    #pragma unroll
    for (int t = 0; t < 4; t++) {
        int idx = tid + t * 256;
        int r = idx >> 4, c4 = (idx & 15) * 4;
        cp_async16(&qs[r * ALDK + c4], &QVb[(size_t)r * EE + c4]);
    }
    CP_COMMIT();

    float Oa[4][2][4] = {};
    float lacc[4][2] = {};

    const int njt = 2 * it + 2;
    for (int jt = 0; jt < njt; jt++) {
        const int j0 = jt * 64;

        CP_WAIT(0);          // qs(jt) (and ks on jt=0) arrived
        __syncthreads();     // all warps done with PV(jt-1) -> vs/ps writable

        // issue vs(jt), consumed after mid barrier; hidden under S-mma+exp
        #pragma unroll
        for (int t = 0; t < 4; t++) {
            int idx = tid + t * 256;
            int r = idx >> 4, c4 = (idx & 15) * 4;
            cp_async16(&vs[r * ALDV + c4], &Vb[(size_t)(j0 + r) * EE + c4]);
        }
        CP_COMMIT();

        // ---- S = K @ QV^T  (M=128 i, N=64 j, K=64 p)
        float Sa[4][2][4] = {};
        #pragma unroll
        for (int kss = 0; kss < 8; kss++) {
            const int kk = kss * 8;
            uint32_t af[4][4], bf[2][2];
            #pragma unroll
            for (int mt = 0; mt < 4; mt++) {
                int r = rbase + mt * 16 + gid;
                af[mt][0] = __float_as_uint(ks[r * ALDK + kk + tig]);
                af[mt][1] = __float_as_uint(ks[(r + 8) * ALDK + kk + tig]);
                af[mt][2] = __float_as_uint(ks[r * ALDK + kk + tig + 4]);
                af[mt][3] = __float_as_uint(ks[(r + 8) * ALDK + kk + tig + 4]);
            }
            #pragma unroll
            for (int nt = 0; nt < 2; nt++) {
                int n = cbase + nt * 8 + gid;
                bf[nt][0] = __float_as_uint(qs[n * ALDK + kk + tig]);
                bf[nt][1] = __float_as_uint(qs[n * ALDK + kk + tig + 4]);
            }
            #pragma unroll
            for (int mt = 0; mt < 4; mt++)
                #pragma unroll
                for (int nt = 0; nt < 2; nt++)
                    mma_tf32(Sa[mt][nt], af[mt], bf[nt]);
        }

        // ---- mask + exp, write P tile (tf32), accumulate row sums
        const bool need_mask = (jt >= 2 * it);
        #pragma unroll
        for (int mt = 0; mt < 4; mt++) {
            #pragma unroll
            for (int nt = 0; nt < 2; nt++) {
                int rr0 = rbase + mt * 16 + gid;
                int cc = cbase + nt * 8 + 2 * tig;
                int iglob0 = i0 + rr0, iglob1 = iglob0 + 8;
                int jg = j0 + cc;
                float e0 = __expf(Sa[mt][nt][0] * scale);
                float e1 = __expf(Sa[mt][nt][1] * scale);
                float e2 = __expf(Sa[mt][nt][2] * scale);
                float e3 = __expf(Sa[mt][nt][3] * scale);
                if (need_mask) {
                    if (jg     > iglob0) e0 = 0.0f;
                    if (jg + 1 > iglob0) e1 = 0.0f;
                    if (jg     > iglob1) e2 = 0.0f;
                    if (jg + 1 > iglob1) e3 = 0.0f;
                }
                lacc[mt][0] += e0 + e1;
                lacc[mt][1] += e2 + e3;
                *(float2*)&ps[rr0 * ALDK + cc] =
                    make_float2(rnd_tf32(e0), rnd_tf32(e1));
                *(float2*)&ps[(rr0 + 8) * ALDK + cc] =
                    make_float2(rnd_tf32(e2), rnd_tf32(e3));
            }
        }
        CP_WAIT(0);          // vs(jt) arrived (hidden behind S-mma + exp)
        __syncthreads();     // P tile complete, vs visible

        // ---- O += P @ V  (M=128 i, N=64 p, K=64 j)
        #pragma unroll
        for (int kss = 0; kss < 8; kss++) {
            const int kk = kss * 8;
            uint32_t af[4][4], bf[2][2];
            #pragma unroll
            for (int mt = 0; mt < 4; mt++) {
                int r = rbase + mt * 16 + gid;
                af[mt][0] = __float_as_uint(ps[r * ALDK + kk + tig]);
                af[mt][1] = __float_as_uint(ps[(r + 8) * ALDK + kk + tig]);
                af[mt][2] = __float_as_uint(ps[r * ALDK + kk + tig + 4]);
                af[mt][3] = __float_as_uint(ps[(r + 8) * ALDK + kk + tig + 4]);
            }
            #pragma unroll
            for (int nt = 0; nt < 2; nt++) {
                int n = cbase + nt * 8 + gid;
                bf[nt][0] = __float_as_uint(vs[(kk + tig) * ALDV + n]);
                bf[nt][1] = __float_as_uint(vs[(kk + tig + 4) * ALDV + n]);
            }
            #pragma unroll
            for (int mt = 0; mt < 4; mt++)
                #pragma unroll
                for (int nt = 0; nt < 2; nt++)
                    mma_tf32(Oa[mt][nt], af[mt], bf[nt]);
        }

        // issue qs(jt+1) — all qs(jt) reads retired before the mid barrier;
        // writes race with nothing (next top barrier orders consumers).
        if (jt + 1 < njt) {
            const int jn = (jt + 1) * 64;
            #pragma unroll
            for (int t = 0; t < 4; t++) {
                int idx = tid + t * 256;
                int r = idx >> 4, c4 = (idx & 15) * 4;
                cp_async16(&qs[r * ALDK + c4], &QVb[(size_t)(jn + r) * EE + c4]);
            }
        }
        CP_COMMIT();
    }

    // ---- reduce l: quad shuffle, then across the 4 wn warps via smem
    #pragma unroll
    for (int mt = 0; mt < 4; mt++) {
        #pragma unroll
        for (int rr = 0; rr < 2; rr++) {
            float v = lacc[mt][rr];
            v += __shfl_xor_sync(0xffffffffu, v, 1);
            v += __shfl_xor_sync(0xffffffffu, v, 2);
            lacc[mt][rr] = v;
        }
    }
    __syncthreads();
    if (tig == 0) {
        #pragma unroll
        for (int mt = 0; mt < 4; mt++) {
            int r = rbase + mt * 16 + gid;
            lsm[r * 4 + wn] = lacc[mt][0];
            lsm[(r + 8) * 4 + wn] = lacc[mt][1];
        }
    }
    __syncthreads();

    float* Ab = g_At + (size_t)b * SS * EE + h * PP;
    #pragma unroll
    for (int mt = 0; mt < 4; mt++) {
        int r = rbase + mt * 16 + gid;
        float inv0 = 1.0f / (lsm[r * 4] + lsm[r * 4 + 1] + lsm[r * 4 + 2] + lsm[r * 4 + 3]);
        int r8 = r + 8;
        float inv1 = 1.0f / (lsm[r8 * 4] + lsm[r8 * 4 + 1] + lsm[r8 * 4 + 2] + lsm[r8 * 4 + 3]);
        #pragma unroll
        for (int nt = 0; nt < 2; nt++) {
            int c = cbase + nt * 8 + 2 * tig;
            *(float2*)&Ab[(size_t)(i0 + r) * EE + c] =
                make_float2(rnd_tf32(Oa[mt][nt][0] * inv0), rnd_tf32(Oa[mt][nt][1] * inv0));
            *(float2*)&Ab[(size_t)(i0 + r8) * EE + c] =
                make_float2(rnd_tf32(Oa[mt][nt][2] * inv1), rnd_tf32(Oa[mt][nt][3] * inv1));
        }
    }
}

// ---------------------------------------------------------------------------
extern "C" void kernel_launch(void* const* d_in, const int* in_sizes, int n_in,
                              void* d_out, int out_size)
{
    const float* x    = (const float*)d_in[0];
    const float* wk   = (const float*)d_in[1];
    const float* wv   = (const float*)d_in[2];
    const float* q    = (const float*)d_in[3];
    const float* lift = (const float*)d_in[4];
    float* out = (float*)d_out;

    static bool attr_done = false;
    if (!attr_done) {
        cudaFuncSetAttribute(gemm_tf32_kernel<0,0>,
            cudaFuncAttributeMaxDynamicSharedMemorySize, GEMM_SMEM);
        cudaFuncSetAttribute(gemm_tf32_kernel<1,1>,
            cudaFuncAttributeMaxDynamicSharedMemorySize, GEMM_SMEM);
        cudaFuncSetAttribute(qv_tf32_kernel,
            cudaFuncAttributeMaxDynamicSharedMemorySize, GEMM_SMEM);
        cudaFuncSetAttribute(attn_mma_kernel,
            cudaFuncAttributeMaxDynamicSharedMemorySize, ATT_SMEM);
        attr_done = true;
    }

    float *gK, *gV, *gAt, *gXt, *gQt, *gWkt, *gWvt, *gLtt;
    cudaGetSymbolAddress((void**)&gK,  g_K);
    cudaGetSymbolAddress((void**)&gV,  g_V);
    cudaGetSymbolAddress((void**)&gAt, g_At);
    cudaGetSymbolAddress((void**)&gXt, g_Xt);
    cudaGetSymbolAddress((void**)&gQt, g_Qt);
    cudaGetSymbolAddress((void**)&gWkt, g_Wkt);
    cudaGetSymbolAddress((void**)&gWvt, g_Wvt);
    cudaGetSymbolAddress((void**)&gLtt, g_Ltt);

    // --- prepass: tf32-round all mma inputs
    auto launch_round = [&](const float* src, float* dst, int n) {
        int n4 = n / 4;
        round_kernel<<<(n4 + 255) / 256, 256>>>(src, dst, n4);
    };
    launch_round(x,    gXt,  BB * SS * EE);
    launch_round(q,    gQt,  HH * SS * SS);
    launch_round(wk,   gWkt, HH * EE * PP);
    launch_round(wv,   gWvt, HH * EE * PP);
    launch_round(lift, gLtt, EE * EE);

    const int M = BB * SS;

    // --- K/V projections (head-packed B), round outputs
    dim3 gp(EE / BN, M / BM);
    gemm_tf32_kernel<1,1><<<gp, 256, GEMM_SMEM>>>(gXt, gWkt, gK, EE, EE, 0, EE);
    gemm_tf32_kernel<1,1><<<gp, 256, GEMM_SMEM>>>(gXt, gWvt, gV, EE, EE, 0, EE);

    // --- QV = Q_h @ Vcat per head
    dim3 gq((BB * PP) / BN, SS / BM, HH);
    qv_tf32_kernel<<<gq, 256, GEMM_SMEM>>>();

    // --- causal attention (tensor core)
    dim3 ga(SS / 128, HH, BB);
    attn_mma_kernel<<<ga, 256, ATT_SMEM>>>();

    // --- out = attn @ lifting (fp32 output, no rounding)
    gemm_tf32_kernel<0,0><<<gp, 256, GEMM_SMEM>>>(gAt, gLtt, out, EE, EE, EE, EE);
}

// round 8
// speedup vs baseline: 4.7129x; 1.0080x over previous
#include <cuda_runtime.h>
#include <cuda_bf16.h>
#include <cstdint>

#define BB 8
#define SS 1024
#define EE 768
#define HH 12
#define PP 64

// ---------------------------------------------------------------------------
// Scratch (__device__ globals; allocation-free rule)
// ---------------------------------------------------------------------------
__device__ float g_K  [BB*SS*EE];   // tf32-rounded, [b][s][h][p]
__device__ float g_V  [BB*SS*EE];   // tf32-rounded
__device__ float g_QV [BB*SS*EE];   // tf32-rounded
__device__ float g_At [BB*SS*EE];   // tf32-rounded
__device__ float g_Xt [BB*SS*EE];   // tf32-rounded copy of x
__device__ float g_Qt [HH*SS*SS];   // tf32-rounded copy of q_heads
__device__ float g_Wkt[HH*EE*PP];
__device__ float g_Wvt[HH*EE*PP];
__device__ float g_Ltt[EE*EE];

// ---------------------------------------------------------------------------
// helpers
// ---------------------------------------------------------------------------
__device__ __forceinline__ uint32_t f2tf32(float f) {
    uint32_t u;
    asm("cvt.rna.tf32.f32 %0, %1;" : "=r"(u) : "f"(f));
    return u;
}
__device__ __forceinline__ float rnd_tf32(float f) {
    return __uint_as_float(f2tf32(f));
}
__device__ __forceinline__ void mma_tf32(float c[4], const uint32_t a[4],
                                         const uint32_t b[2]) {
    asm volatile(
        "mma.sync.aligned.m16n8k8.row.col.f32.tf32.tf32.f32 "
        "{%0,%1,%2,%3}, {%4,%5,%6,%7}, {%8,%9}, {%0,%1,%2,%3};"
        : "+f"(c[0]), "+f"(c[1]), "+f"(c[2]), "+f"(c[3])
        : "r"(a[0]), "r"(a[1]), "r"(a[2]), "r"(a[3]), "r"(b[0]), "r"(b[1]));
}
__device__ __forceinline__ void cp_async16(void* sptr, const void* gptr) {
    uint32_t s = (uint32_t)__cvta_generic_to_shared(sptr);
    asm volatile("cp.async.cg.shared.global [%0], [%1], 16;\n"
                 :: "r"(s), "l"(gptr) : "memory");
}
#define CP_COMMIT() asm volatile("cp.async.commit_group;\n" ::: "memory")
#define CP_WAIT(n)  asm volatile("cp.async.wait_group %0;\n" :: "n"(n) : "memory")

// ---------------------------------------------------------------------------
// Prepass: ONE segmented tf32-rounding sweep over all five inputs
// ---------------------------------------------------------------------------
#define N4_X  ((BB*SS*EE)/4)
#define N4_Q  ((HH*SS*SS)/4)
#define N4_W  ((HH*EE*PP)/4)
#define N4_L  ((EE*EE)/4)
#define N4_TOT (N4_X + N4_Q + 2*N4_W + N4_L)

__global__ void round_all_kernel(
    const float4* __restrict__ x,  const float4* __restrict__ q,
    const float4* __restrict__ wk, const float4* __restrict__ wv,
    const float4* __restrict__ lf,
    float4* __restrict__ ox,  float4* __restrict__ oq,
    float4* __restrict__ owk, float4* __restrict__ owv,
    float4* __restrict__ olf)
{
    int i = blockIdx.x * blockDim.x + threadIdx.x;
    const float4* src; float4* dst; int li;
    if (i < N4_X) { src = x; dst = ox; li = i; }
    else if (i < N4_X + N4_Q) { src = q; dst = oq; li = i - N4_X; }
    else if (i < N4_X + N4_Q + N4_W) { src = wk; dst = owk; li = i - N4_X - N4_Q; }
    else if (i < N4_X + N4_Q + 2*N4_W) { src = wv; dst = owv; li = i - N4_X - N4_Q - N4_W; }
    else if (i < N4_TOT) { src = lf; dst = olf; li = i - N4_X - N4_Q - 2*N4_W; }
    else return;
    float4 v = src[li];
    v.x = rnd_tf32(v.x); v.y = rnd_tf32(v.y);
    v.z = rnd_tf32(v.z); v.w = rnd_tf32(v.w);
    dst[li] = v;
}

// ---------------------------------------------------------------------------
// TF32 GEMM, 3-stage cp.async pipeline, 1 __syncthreads per k-tile.
// ---------------------------------------------------------------------------
#define BM 128
#define BN 128
#define BK 32
#define LDA 36
#define LDB 136
#define STAGES 3
#define GEMM_SMEM ((STAGES*(BM*LDA + BK*LDB)) * 4)

// ---- fused K/V projection: blockIdx.z selects (Wk->g_K) or (Wv->g_V).
// B head-packed: B[k][n] = w[(n>>6)*EE*64 + k*64 + (n&63)].
// Output rounded to tf32. grid (EE/BN, M/BM, 2), 256 threads.
__global__ __launch_bounds__(256, 2) void proj_tf32_kernel(
    const float* __restrict__ A,
    const float* __restrict__ Bk, const float* __restrict__ Bv,
    float* __restrict__ Ck, float* __restrict__ Cv)
{
    extern __shared__ float smx[];
    float* As = smx;
    float* Bs = smx + STAGES * BM * LDA;

    const float* Bm = blockIdx.z ? Bv : Bk;
    float* C = blockIdx.z ? Cv : Ck;

    const int tid = threadIdx.x;
    const int wid = tid >> 5, lane = tid & 31;
    const int gid = lane >> 2, tig = lane & 3;
    const int warp_m = (wid >> 2) * 64;
    const int warp_n = (wid & 3) * 32;
    const int m0 = blockIdx.y * BM, n0 = blockIdx.x * BN;

    float acc[4][4][4] = {};

    auto load_tile = [&](int k0, int stage) {
        float* Ad = As + stage * (BM * LDA);
        float* Bd = Bs + stage * (BK * LDB);
        #pragma unroll
        for (int i = 0; i < 4; i++) {
            int f4 = tid + i * 256;
            int m = f4 >> 3, kc = (f4 & 7) * 4;
            cp_async16(&Ad[m * LDA + kc], &A[(size_t)(m0 + m) * EE + k0 + kc]);
        }
        #pragma unroll
        for (int i = 0; i < 4; i++) {
            int f4 = tid + i * 256;
            int k = f4 >> 5, nc = (f4 & 31) * 4;
            int n = n0 + nc;
            cp_async16(&Bd[k * LDB + nc],
                       &Bm[(size_t)(n >> 6) * (EE * 64) + (k0 + k) * 64 + (n & 63)]);
        }
    };

    const int ntiles = EE / BK;
    load_tile(0, 0); CP_COMMIT();
    load_tile(BK, 1); CP_COMMIT();

    for (int kt = 0; kt < ntiles; kt++) {
        CP_WAIT(1);
        __syncthreads();
        if (kt + 2 < ntiles) {
            int s = (kt + 2) % STAGES;
            load_tile((kt + 2) * BK, s);
        }
        CP_COMMIT();

        const float* Ad = As + (kt % STAGES) * (BM * LDA);
        const float* Bd = Bs + (kt % STAGES) * (BK * LDB);
        #pragma unroll
        for (int ks = 0; ks < BK / 8; ks++) {
            const int kk = ks * 8;
            uint32_t af[4][4], bf[4][2];
            #pragma unroll
            for (int mt = 0; mt < 4; mt++) {
                int r = warp_m + mt * 16 + gid;
                af[mt][0] = __float_as_uint(Ad[r * LDA + kk + tig]);
                af[mt][1] = __float_as_uint(Ad[(r + 8) * LDA + kk + tig]);
                af[mt][2] = __float_as_uint(Ad[r * LDA + kk + tig + 4]);
                af[mt][3] = __float_as_uint(Ad[(r + 8) * LDA + kk + tig + 4]);
            }
            #pragma unroll
            for (int nt = 0; nt < 4; nt++) {
                int n = warp_n + nt * 8 + gid;
                bf[nt][0] = __float_as_uint(Bd[(kk + tig) * LDB + n]);
                bf[nt][1] = __float_as_uint(Bd[(kk + tig + 4) * LDB + n]);
            }
            #pragma unroll
            for (int mt = 0; mt < 4; mt++)
                #pragma unroll
                for (int nt = 0; nt < 4; nt++)
                    mma_tf32(acc[mt][nt], af[mt], bf[nt]);
        }
    }

    __syncthreads();
    #pragma unroll
    for (int mt = 0; mt < 4; mt++) {
        int r = m0 + warp_m + mt * 16 + gid;
        #pragma unroll
        for (int nt = 0; nt < 4; nt++) {
            int c = n0 + warp_n + nt * 8 + tig * 2;
            *(float2*)&C[(size_t)r * EE + c] =
                make_float2(rnd_tf32(acc[mt][nt][0]), rnd_tf32(acc[mt][nt][1]));
            *(float2*)&C[(size_t)(r + 8) * EE + c] =
                make_float2(rnd_tf32(acc[mt][nt][2]), rnd_tf32(acc[mt][nt][3]));
        }
    }
}

// ---- plain GEMM (lift): C = A(8192x768) @ B(768x768), fp32 out.
__global__ __launch_bounds__(256, 2) void lift_tf32_kernel(
    const float* __restrict__ A, const float* __restrict__ Bm,
    float* __restrict__ C)
{
    extern __shared__ float smx[];
    float* As = smx;
    float* Bs = smx + STAGES * BM * LDA;

    const int tid = threadIdx.x;
    const int wid = tid >> 5, lane = tid & 31;
    const int gid = lane >> 2, tig = lane & 3;
    const int warp_m = (wid >> 2) * 64;
    const int warp_n = (wid & 3) * 32;
    const int m0 = blockIdx.y * BM, n0 = blockIdx.x * BN;

    float acc[4][4][4] = {};

    auto load_tile = [&](int k0, int stage) {
        float* Ad = As + stage * (BM * LDA);
        float* Bd = Bs + stage * (BK * LDB);
        #pragma unroll
        for (int i = 0; i < 4; i++) {
            int f4 = tid + i * 256;
            int m = f4 >> 3, kc = (f4 & 7) * 4;
            cp_async16(&Ad[m * LDA + kc], &A[(size_t)(m0 + m) * EE + k0 + kc]);
        }
        #pragma unroll
        for (int i = 0; i < 4; i++) {
            int f4 = tid + i * 256;
            int k = f4 >> 5, nc = (f4 & 31) * 4;
            cp_async16(&Bd[k * LDB + nc], &Bm[(size_t)(k0 + k) * EE + n0 + nc]);
        }
    };

    const int ntiles = EE / BK;
    load_tile(0, 0); CP_COMMIT();
    load_tile(BK, 1); CP_COMMIT();

    for (int kt = 0; kt < ntiles; kt++) {
        CP_WAIT(1);
        __syncthreads();
        if (kt + 2 < ntiles) {
            int s = (kt + 2) % STAGES;
            load_tile((kt + 2) * BK, s);
        }
        CP_COMMIT();

        const float* Ad = As + (kt % STAGES) * (BM * LDA);
        const float* Bd = Bs + (kt % STAGES) * (BK * LDB);
        #pragma unroll
        for (int ks = 0; ks < BK / 8; ks++) {
            const int kk = ks * 8;
            uint32_t af[4][4], bf[4][2];
            #pragma unroll
            for (int mt = 0; mt < 4; mt++) {
                int r = warp_m + mt * 16 + gid;
                af[mt][0] = __float_as_uint(Ad[r * LDA + kk + tig]);
                af[mt][1] = __float_as_uint(Ad[(r + 8) * LDA + kk + tig]);
                af[mt][2] = __float_as_uint(Ad[r * LDA + kk + tig + 4]);
                af[mt][3] = __float_as_uint(Ad[(r + 8) * LDA + kk + tig + 4]);
            }
            #pragma unroll
            for (int nt = 0; nt < 4; nt++) {
                int n = warp_n + nt * 8 + gid;
                bf[nt][0] = __float_as_uint(Bd[(kk + tig) * LDB + n]);
                bf[nt][1] = __float_as_uint(Bd[(kk + tig + 4) * LDB + n]);
            }
            #pragma unroll
            for (int mt = 0; mt < 4; mt++)
                #pragma unroll
                for (int nt = 0; nt < 4; nt++)
                    mma_tf32(acc[mt][nt], af[mt], bf[nt]);
        }
    }

    __syncthreads();
    #pragma unroll
    for (int mt = 0; mt < 4; mt++) {
        int r = m0 + warp_m + mt * 16 + gid;
        #pragma unroll
        for (int nt = 0; nt < 4; nt++) {
            int c = n0 + warp_n + nt * 8 + tig * 2;
            *(float2*)&C[(size_t)r * EE + c] =
                make_float2(acc[mt][nt][0], acc[mt][nt][1]);
            *(float2*)&C[(size_t)(r + 8) * EE + c] =
                make_float2(acc[mt][nt][2], acc[mt][nt][3]);
        }
    }
}

// ---------------------------------------------------------------------------
// QV GEMM per head, 3-stage pipeline:
//   QVcat(1024 x 512) = Q_h(1024x1024) @ Vcat(1024x512)
//   Vcat[k][n] = g_V[((n>>6)*SS + k)*EE + h*PP + (n&63)]
// grid (4, 8, 12), 256 threads.
// ---------------------------------------------------------------------------
__global__ __launch_bounds__(256, 2) void qv_tf32_kernel()
{
    extern __shared__ float smx[];
    float* As = smx;
    float* Bs = smx + STAGES * BM * LDA;

    const int h = blockIdx.z;
    const int tid = threadIdx.x;
    const int wid = tid >> 5, lane = tid & 31;
    const int gid = lane >> 2, tig = lane & 3;
    const int warp_m = (wid >> 2) * 64;
    const int warp_n = (wid & 3) * 32;
    const int m0 = blockIdx.y * BM, n0 = blockIdx.x * BN;

    const float* A  = g_Qt + (size_t)h * SS * SS;
    const float* Vb = g_V + h * PP;

    float acc[4][4][4] = {};

    auto load_tile = [&](int k0, int stage) {
        float* Ad = As + stage * (BM * LDA);
        float* Bd = Bs + stage * (BK * LDB);
        #pragma unroll
        for (int i = 0; i < 4; i++) {
            int f4 = tid + i * 256;
            int m = f4 >> 3, kc = (f4 & 7) * 4;
            cp_async16(&Ad[m * LDA + kc], &A[(size_t)(m0 + m) * SS + k0 + kc]);
        }
        #pragma unroll
        for (int i = 0; i < 4; i++) {
            int f4 = tid + i * 256;
            int k = f4 >> 5, nc = (f4 & 31) * 4;
            int n = n0 + nc;
            cp_async16(&Bd[k * LDB + nc],
                       &Vb[(size_t)((n >> 6) * SS + k0 + k) * EE + (n & 63)]);
        }
    };

    const int ntiles = SS / BK;
    load_tile(0, 0); CP_COMMIT();
    load_tile(BK, 1); CP_COMMIT();

    for (int kt = 0; kt < ntiles; kt++) {
        CP_WAIT(1);
        __syncthreads();
        if (kt + 2 < ntiles) {
            int s = (kt + 2) % STAGES;
            load_tile((kt + 2) * BK, s);
        }
        CP_COMMIT();

        const float* Ad = As + (kt % STAGES) * (BM * LDA);
        const float* Bd = Bs + (kt % STAGES) * (BK * LDB);
        #pragma unroll
        for (int ks = 0; ks < BK / 8; ks++) {
            const int kk = ks * 8;
            uint32_t af[4][4], bf[4][2];
            #pragma unroll
            for (int mt = 0; mt < 4; mt++) {
                int r = warp_m + mt * 16 + gid;
                af[mt][0] = __float_as_uint(Ad[r * LDA + kk + tig]);
                af[mt][1] = __float_as_uint(Ad[(r + 8) * LDA + kk + tig]);
                af[mt][2] = __float_as_uint(Ad[r * LDA + kk + tig + 4]);
                af[mt][3] = __float_as_uint(Ad[(r + 8) * LDA + kk + tig + 4]);
            }
            #pragma unroll
            for (int nt = 0; nt < 4; nt++) {
                int n = warp_n + nt * 8 + gid;
                bf[nt][0] = __float_as_uint(Bd[(kk + tig) * LDB + n]);
                bf[nt][1] = __float_as_uint(Bd[(kk + tig + 4) * LDB + n]);
            }
            #pragma unroll
            for (int mt = 0; mt < 4; mt++)
                #pragma unroll
                for (int nt = 0; nt < 4; nt++)
                    mma_tf32(acc[mt][nt], af[mt], bf[nt]);
        }
    }

    __syncthreads();
    float* QVb = g_QV + h * PP;
    #pragma unroll
    for (int mt = 0; mt < 4; mt++) {
        int r = m0 + warp_m + mt * 16 + gid;
        #pragma unroll
        for (int nt = 0; nt < 4; nt++) {
            int n = n0 + warp_n + nt * 8 + tig * 2;
            int b_ = n >> 6, p = n & 63;
            *(float2*)&QVb[(size_t)(b_ * SS + r) * EE + p] =
                make_float2(rnd_tf32(acc[mt][nt][0]), rnd_tf32(acc[mt][nt][1]));
            *(float2*)&QVb[(size_t)(b_ * SS + r + 8) * EE + p] =
                make_float2(rnd_tf32(acc[mt][nt][2]), rnd_tf32(acc[mt][nt][3]));
        }
    }
}

// ---------------------------------------------------------------------------
// Tensor-core causal attention (race-fixed schedule; verified R6).
// ---------------------------------------------------------------------------
#define ALDK 68
#define ALDV 72
#define ATT_SMEM ((128*ALDK + 64*ALDK + 64*ALDV + 128*ALDK + 128*4) * 4)

__global__ __launch_bounds__(256, 2) void attn_mma_kernel()
{
    extern __shared__ float sm[];
    float* ks  = sm;                       // 128 x 68
    float* qs  = ks + 128 * ALDK;          // 64 x 68
    float* vs  = qs + 64 * ALDK;           // 64 x 72
    float* ps  = vs + 64 * ALDV;           // 128 x 68
    float* lsm = ps + 128 * ALDK;          // 128 x 4

    const int it = 7 - (int)blockIdx.x;    // heavy blocks first
    const int h = blockIdx.y, b = blockIdx.z;
    const int i0 = it * 128;
    const int tid = threadIdx.x;
    const int wid = tid >> 5, lane = tid & 31;
    const int gid = lane >> 2, tig = lane & 3;
    const int wm = wid >> 2, wn = wid & 3;
    const int rbase = wm * 64;
    const int cbase = wn * 16;
    const float scale = 0.03608439182435161f;  // 1/sqrt(768)

    const float* Kb  = g_K  + (size_t)b * SS * EE + h * PP;
    const float* QVb = g_QV + (size_t)b * SS * EE + h * PP;
    const float* Vb  = g_V  + (size_t)b * SS * EE + h * PP;

    #pragma unroll
    for (int t = 0; t < 8; t++) {
        int idx = tid + t * 256;
        int r = idx >> 4, c4 = (idx & 15) * 4;
        cp_async16(&ks[r * ALDK + c4], &Kb[(size_t)(i0 + r) * EE + c4]);
    }
    CP_COMMIT();

    #pragma unroll
    for (int t = 0; t < 4; t++) {
        int idx = tid + t * 256;
        int r = idx >> 4, c4 = (idx & 15) * 4;
        cp_async16(&qs[r * ALDK + c4], &QVb[(size_t)r * EE + c4]);
    }
    CP_COMMIT();

    float Oa[4][2][4] = {};
    float lacc[4][2] = {};

    const int njt = 2 * it + 2;
    for (int jt = 0; jt < njt; jt++) {
        const int j0 = jt * 64;

        CP_WAIT(0);          // qs(jt) (and ks on jt=0) arrived
        __syncthreads();     // all warps done with PV(jt-1) -> vs/ps writable

        #pragma unroll
        for (int t = 0; t < 4; t++) {
            int idx = tid + t * 256;
            int r = idx >> 4, c4 = (idx & 15) * 4;
            cp_async16(&vs[r * ALDV + c4], &Vb[(size_t)(j0 + r) * EE + c4]);
        }
        CP_COMMIT();

        float Sa[4][2][4] = {};
        #pragma unroll
        for (int kss = 0; kss < 8; kss++) {
            const int kk = kss * 8;
            uint32_t af[4][4], bf[2][2];
            #pragma unroll
            for (int mt = 0; mt < 4; mt++) {
                int r = rbase + mt * 16 + gid;
                af[mt][0] = __float_as_uint(ks[r * ALDK + kk + tig]);
                af[mt][1] = __float_as_uint(ks[(r + 8) * ALDK + kk + tig]);
                af[mt][2] = __float_as_uint(ks[r * ALDK + kk + tig + 4]);
                af[mt][3] = __float_as_uint(ks[(r + 8) * ALDK + kk + tig + 4]);
            }
            #pragma unroll
            for (int nt = 0; nt < 2; nt++) {
                int n = cbase + nt * 8 + gid;
                bf[nt][0] = __float_as_uint(qs[n * ALDK + kk + tig]);
                bf[nt][1] = __float_as_uint(qs[n * ALDK + kk + tig + 4]);
            }
            #pragma unroll
            for (int mt = 0; mt < 4; mt++)
                #pragma unroll
                for (int nt = 0; nt < 2; nt++)
                    mma_tf32(Sa[mt][nt], af[mt], bf[nt]);
        }

        const bool need_mask = (jt >= 2 * it);
        #pragma unroll
        for (int mt = 0; mt < 4; mt++) {
            #pragma unroll
            for (int nt = 0; nt < 2; nt++) {
                int rr0 = rbase + mt * 16 + gid;
                int cc = cbase + nt * 8 + 2 * tig;
                int iglob0 = i0 + rr0, iglob1 = iglob0 + 8;
                int jg = j0 + cc;
                float e0 = __expf(Sa[mt][nt][0] * scale);
                float e1 = __expf(Sa[mt][nt][1] * scale);
                float e2 = __expf(Sa[mt][nt][2] * scale);
                float e3 = __expf(Sa[mt][nt][3] * scale);
                if (need_mask) {
                    if (jg     > iglob0) e0 = 0.0f;
                    if (jg + 1 > iglob0) e1 = 0.0f;
                    if (jg     > iglob1) e2 = 0.0f;
                    if (jg + 1 > iglob1) e3 = 0.0f;
                }
                lacc[mt][0] += e0 + e1;
                lacc[mt][1] += e2 + e3;
                *(float2*)&ps[rr0 * ALDK + cc] =
                    make_float2(rnd_tf32(e0), rnd_tf32(e1));
                *(float2*)&ps[(rr0 + 8) * ALDK + cc] =
                    make_float2(rnd_tf32(e2), rnd_tf32(e3));
            }
        }
        CP_WAIT(0);          // vs(jt) arrived (hidden behind S-mma + exp)
        __syncthreads();     // P tile complete, vs visible

        #pragma unroll
        for (int kss = 0; kss < 8; kss++) {
            const int kk = kss * 8;
            uint32_t af[4][4], bf[2][2];
            #pragma unroll
            for (int mt = 0; mt < 4; mt++) {
                int r = rbase + mt * 16 + gid;
                af[mt][0] = __float_as_uint(ps[r * ALDK + kk + tig]);
                af[mt][1] = __float_as_uint(ps[(r + 8) * ALDK + kk + tig]);
                af[mt][2] = __float_as_uint(ps[r * ALDK + kk + tig + 4]);
                af[mt][3] = __float_as_uint(ps[(r + 8) * ALDK + kk + tig + 4]);
            }
            #pragma unroll
            for (int nt = 0; nt < 2; nt++) {
                int n = cbase + nt * 8 + gid;
                bf[nt][0] = __float_as_uint(vs[(kk + tig) * ALDV + n]);
                bf[nt][1] = __float_as_uint(vs[(kk + tig + 4) * ALDV + n]);
            }
            #pragma unroll
            for (int mt = 0; mt < 4; mt++)
                #pragma unroll
                for (int nt = 0; nt < 2; nt++)
                    mma_tf32(Oa[mt][nt], af[mt], bf[nt]);
        }

        if (jt + 1 < njt) {
            const int jn = (jt + 1) * 64;
            #pragma unroll
            for (int t = 0; t < 4; t++) {
                int idx = tid + t * 256;
                int r = idx >> 4, c4 = (idx & 15) * 4;
                cp_async16(&qs[r * ALDK + c4], &QVb[(size_t)(jn + r) * EE + c4]);
            }
        }
        CP_COMMIT();
    }

    #pragma unroll
    for (int mt = 0; mt < 4; mt++) {
        #pragma unroll
        for (int rr = 0; rr < 2; rr++) {
            float v = lacc[mt][rr];
            v += __shfl_xor_sync(0xffffffffu, v, 1);
            v += __shfl_xor_sync(0xffffffffu, v, 2);
            lacc[mt][rr] = v;
        }
    }
    __syncthreads();
    if (tig == 0) {
        #pragma unroll
        for (int mt = 0; mt < 4; mt++) {
            int r = rbase + mt * 16 + gid;
            lsm[r * 4 + wn] = lacc[mt][0];
            lsm[(r + 8) * 4 + wn] = lacc[mt][1];
        }
    }
    __syncthreads();

    float* Ab = g_At + (size_t)b * SS * EE + h * PP;
    #pragma unroll
    for (int mt = 0; mt < 4; mt++) {
        int r = rbase + mt * 16 + gid;
        float inv0 = 1.0f / (lsm[r * 4] + lsm[r * 4 + 1] + lsm[r * 4 + 2] + lsm[r * 4 + 3]);
        int r8 = r + 8;
        float inv1 = 1.0f / (lsm[r8 * 4] + lsm[r8 * 4 + 1] + lsm[r8 * 4 + 2] + lsm[r8 * 4 + 3]);
        #pragma unroll
        for (int nt = 0; nt < 2; nt++) {
            int c = cbase + nt * 8 + 2 * tig;
            *(float2*)&Ab[(size_t)(i0 + r) * EE + c] =
                make_float2(rnd_tf32(Oa[mt][nt][0] * inv0), rnd_tf32(Oa[mt][nt][1] * inv0));
            *(float2*)&Ab[(size_t)(i0 + r8) * EE + c] =
                make_float2(rnd_tf32(Oa[mt][nt][2] * inv1), rnd_tf32(Oa[mt][nt][3] * inv1));
        }
    }
}

// ---------------------------------------------------------------------------
extern "C" void kernel_launch(void* const* d_in, const int* in_sizes, int n_in,
                              void* d_out, int out_size)
{
    const float* x    = (const float*)d_in[0];
    const float* wk   = (const float*)d_in[1];
    const float* wv   = (const float*)d_in[2];
    const float* q    = (const float*)d_in[3];
    const float* lift = (const float*)d_in[4];
    float* out = (float*)d_out;

    static bool attr_done = false;
    if (!attr_done) {
        cudaFuncSetAttribute(proj_tf32_kernel,
            cudaFuncAttributeMaxDynamicSharedMemorySize, GEMM_SMEM);
        cudaFuncSetAttribute(lift_tf32_kernel,
            cudaFuncAttributeMaxDynamicSharedMemorySize, GEMM_SMEM);
        cudaFuncSetAttribute(qv_tf32_kernel,
            cudaFuncAttributeMaxDynamicSharedMemorySize, GEMM_SMEM);
        cudaFuncSetAttribute(attn_mma_kernel,
            cudaFuncAttributeMaxDynamicSharedMemorySize, ATT_SMEM);
        attr_done = true;
    }

    float *gK, *gV, *gAt, *gXt, *gQt, *gWkt, *gWvt, *gLtt;
    cudaGetSymbolAddress((void**)&gK,  g_K);
    cudaGetSymbolAddress((void**)&gV,  g_V);
    cudaGetSymbolAddress((void**)&gAt, g_At);
    cudaGetSymbolAddress((void**)&gXt, g_Xt);
    cudaGetSymbolAddress((void**)&gQt, g_Qt);
    cudaGetSymbolAddress((void**)&gWkt, g_Wkt);
    cudaGetSymbolAddress((void**)&gWvt, g_Wvt);
    cudaGetSymbolAddress((void**)&gLtt, g_Ltt);

    // --- prepass: ONE segmented tf32-rounding sweep
    round_all_kernel<<<(N4_TOT + 255) / 256, 256>>>(
        (const float4*)x, (const float4*)q, (const float4*)wk,
        (const float4*)wv, (const float4*)lift,
        (float4*)gXt, (float4*)gQt, (float4*)gWkt,
        (float4*)gWvt, (float4*)gLtt);

    const int M = BB * SS;

    // --- fused K/V projections (one launch, 768 CTAs)
    dim3 gp(EE / BN, M / BM, 2);
    proj_tf32_kernel<<<gp, 256, GEMM_SMEM>>>(gXt, gWkt, gWvt, gK, gV);

    // --- QV = Q_h @ Vcat per head
    dim3 gq((BB * PP) / BN, SS / BM, HH);
    qv_tf32_kernel<<<gq, 256, GEMM_SMEM>>>();

    // --- causal attention (tensor core)
    dim3 ga(SS / 128, HH, BB);
    attn_mma_kernel<<<ga, 256, ATT_SMEM>>>();

    // --- out = attn @ lifting (fp32 output)
    dim3 gl(EE / BN, M / BM);
    lift_tf32_kernel<<<gl, 256, GEMM_SMEM>>>(gAt, gLtt, out);
}

// round 9
// speedup vs baseline: 4.7617x; 1.0104x over previous
#include <cuda_runtime.h>
#include <cuda_bf16.h>
#include <cstdint>

#define BB 8
#define SS 1024
#define EE 768
#define HH 12
#define PP 64

// ---------------------------------------------------------------------------
// Scratch (__device__ globals; allocation-free rule)
// ---------------------------------------------------------------------------
__device__ float g_K  [BB*SS*EE];   // tf32-rounded, [b][s][h][p]
__device__ float g_V  [BB*SS*EE];   // tf32-rounded
__device__ float g_QV [BB*SS*EE];   // tf32-rounded
__device__ float g_At [BB*SS*EE];   // tf32-rounded
__device__ float g_Xt [BB*SS*EE];   // tf32-rounded copy of x
__device__ float g_Qt [HH*SS*SS];   // tf32-rounded copy of q_heads
__device__ float g_Wkt[HH*EE*PP];
__device__ float g_Wvt[HH*EE*PP];
__device__ float g_Ltt[EE*EE];

// ---------------------------------------------------------------------------
// helpers
// ---------------------------------------------------------------------------
__device__ __forceinline__ uint32_t f2tf32(float f) {
    uint32_t u;
    asm("cvt.rna.tf32.f32 %0, %1;" : "=r"(u) : "f"(f));
    return u;
}
__device__ __forceinline__ float rnd_tf32(float f) {
    return __uint_as_float(f2tf32(f));
}
__device__ __forceinline__ void mma_tf32(float c[4], const uint32_t a[4],
                                         const uint32_t b[2]) {
    asm volatile(
        "mma.sync.aligned.m16n8k8.row.col.f32.tf32.tf32.f32 "
        "{%0,%1,%2,%3}, {%4,%5,%6,%7}, {%8,%9}, {%0,%1,%2,%3};"
        : "+f"(c[0]), "+f"(c[1]), "+f"(c[2]), "+f"(c[3])
        : "r"(a[0]), "r"(a[1]), "r"(a[2]), "r"(a[3]), "r"(b[0]), "r"(b[1]));
}
__device__ __forceinline__ void cp_async16(void* sptr, const void* gptr) {
    uint32_t s = (uint32_t)__cvta_generic_to_shared(sptr);
    asm volatile("cp.async.cg.shared.global [%0], [%1], 16;\n"
                 :: "r"(s), "l"(gptr) : "memory");
}
#define CP_COMMIT() asm volatile("cp.async.commit_group;\n" ::: "memory")
#define CP_WAIT(n)  asm volatile("cp.async.wait_group %0;\n" :: "n"(n) : "memory")

__device__ __forceinline__ uint32_t smem_u32(const void* p) {
    return (uint32_t)__cvta_generic_to_shared(p);
}
// tf32 fragment loader: 4 8x4-tf32 submatrices (viewed as 8x8 b16 each).
__device__ __forceinline__ void ldsm_x4(uint32_t& r0, uint32_t& r1,
                                        uint32_t& r2, uint32_t& r3, uint32_t a) {
    asm volatile("ldmatrix.sync.aligned.m8n8.x4.shared.b16 {%0,%1,%2,%3}, [%4];"
                 : "=r"(r0), "=r"(r1), "=r"(r2), "=r"(r3) : "r"(a));
}

// ---------------------------------------------------------------------------
// Prepass: ONE segmented tf32-rounding sweep over all five inputs
// ---------------------------------------------------------------------------
#define N4_X  ((BB*SS*EE)/4)
#define N4_Q  ((HH*SS*SS)/4)
#define N4_W  ((HH*EE*PP)/4)
#define N4_L  ((EE*EE)/4)
#define N4_TOT (N4_X + N4_Q + 2*N4_W + N4_L)

__global__ void round_all_kernel(
    const float4* __restrict__ x,  const float4* __restrict__ q,
    const float4* __restrict__ wk, const float4* __restrict__ wv,
    const float4* __restrict__ lf,
    float4* __restrict__ ox,  float4* __restrict__ oq,
    float4* __restrict__ owk, float4* __restrict__ owv,
    float4* __restrict__ olf)
{
    int i = blockIdx.x * blockDim.x + threadIdx.x;
    const float4* src; float4* dst; int li;
    if (i < N4_X) { src = x; dst = ox; li = i; }
    else if (i < N4_X + N4_Q) { src = q; dst = oq; li = i - N4_X; }
    else if (i < N4_X + N4_Q + N4_W) { src = wk; dst = owk; li = i - N4_X - N4_Q; }
    else if (i < N4_X + N4_Q + 2*N4_W) { src = wv; dst = owv; li = i - N4_X - N4_Q - N4_W; }
    else if (i < N4_TOT) { src = lf; dst = olf; li = i - N4_X - N4_Q - 2*N4_W; }
    else return;
    float4 v = src[li];
    v.x = rnd_tf32(v.x); v.y = rnd_tf32(v.y);
    v.z = rnd_tf32(v.z); v.w = rnd_tf32(v.w);
    dst[li] = v;
}

// ---------------------------------------------------------------------------
// GEMM geometry
// ---------------------------------------------------------------------------
#define BN 128
#define BK 32
#define LDA 36
#define LDB 136
#define STAGES 3
#define GEMM_SMEM128 ((STAGES*(128*LDA + BK*LDB)) * 4)
#define GEMM_SMEM64  ((STAGES*( 64*LDA + BK*LDB)) * 4)

// ---------------------------------------------------------------------------
// Fused K/V projection (BM=128): blockIdx.z selects (Wk->g_K)/(Wv->g_V).
// B head-packed: B[k][n] = w[(n>>6)*EE*64 + k*64 + (n&63)]. tf32-rounded out.
// grid (EE/BN, 8192/128, 2), 256 threads.
// ---------------------------------------------------------------------------
__global__ __launch_bounds__(256, 2) void proj_tf32_kernel(
    const float* __restrict__ A,
    const float* __restrict__ Bk, const float* __restrict__ Bv,
    float* __restrict__ Ck, float* __restrict__ Cv)
{
    extern __shared__ float smx[];
    float* As = smx;
    float* Bs = smx + STAGES * 128 * LDA;

    const float* Bm = blockIdx.z ? Bv : Bk;
    float* C = blockIdx.z ? Cv : Ck;

    const int tid = threadIdx.x;
    const int wid = tid >> 5, lane = tid & 31;
    const int gid = lane >> 2, tig = lane & 3;
    const int lr = lane & 7, sub = lane >> 3;
    const int warp_m = (wid >> 2) * 64;
    const int warp_n = (wid & 3) * 32;
    const int m0 = blockIdx.y * 128, n0 = blockIdx.x * BN;

    // per-lane LDSM base offset within an A stage (A-fragment pattern)
    const uint32_t a_lane_off =
        (uint32_t)(((warp_m + lr + (sub & 1) * 8) * LDA + (sub >> 1) * 4) * 4);
    const uint32_t As_u = smem_u32(As);

    float acc[4][4][4] = {};

    auto load_tile = [&](int k0, int stage) {
        float* Ad = As + stage * (128 * LDA);
        float* Bd = Bs + stage * (BK * LDB);
        #pragma unroll
        for (int i = 0; i < 4; i++) {
            int f4 = tid + i * 256;
            int m = f4 >> 3, kc = (f4 & 7) * 4;
            cp_async16(&Ad[m * LDA + kc], &A[(size_t)(m0 + m) * EE + k0 + kc]);
        }
        #pragma unroll
        for (int i = 0; i < 4; i++) {
            int f4 = tid + i * 256;
            int k = f4 >> 5, nc = (f4 & 31) * 4;
            int n = n0 + nc;
            cp_async16(&Bd[k * LDB + nc],
                       &Bm[(size_t)(n >> 6) * (EE * 64) + (k0 + k) * 64 + (n & 63)]);
        }
    };

    const int ntiles = EE / BK;
    load_tile(0, 0); CP_COMMIT();
    load_tile(BK, 1); CP_COMMIT();

    for (int kt = 0; kt < ntiles; kt++) {
        CP_WAIT(1);
        __syncthreads();
        if (kt + 2 < ntiles) {
            int s = (kt + 2) % STAGES;
            load_tile((kt + 2) * BK, s);
        }
        CP_COMMIT();

        const uint32_t a_stage = As_u + (uint32_t)((kt % STAGES) * (128 * LDA) * 4) + a_lane_off;
        const float* Bd = Bs + (kt % STAGES) * (BK * LDB);
        #pragma unroll
        for (int ks = 0; ks < BK / 8; ks++) {
            const int kk = ks * 8;
            uint32_t af[4][4], bf[4][2];
            #pragma unroll
            for (int mt = 0; mt < 4; mt++)
                ldsm_x4(af[mt][0], af[mt][1], af[mt][2], af[mt][3],
                        a_stage + (uint32_t)((mt * 16 * LDA + kk) * 4));
            #pragma unroll
            for (int nt = 0; nt < 4; nt++) {
                int n = warp_n + nt * 8 + gid;
                bf[nt][0] = __float_as_uint(Bd[(kk + tig) * LDB + n]);
                bf[nt][1] = __float_as_uint(Bd[(kk + tig + 4) * LDB + n]);
            }
            #pragma unroll
            for (int mt = 0; mt < 4; mt++)
                #pragma unroll
                for (int nt = 0; nt < 4; nt++)
                    mma_tf32(acc[mt][nt], af[mt], bf[nt]);
        }
    }

    __syncthreads();
    #pragma unroll
    for (int mt = 0; mt < 4; mt++) {
        int r = m0 + warp_m + mt * 16 + gid;
        #pragma unroll
        for (int nt = 0; nt < 4; nt++) {
            int c = n0 + warp_n + nt * 8 + tig * 2;
            *(float2*)&C[(size_t)r * EE + c] =
                make_float2(rnd_tf32(acc[mt][nt][0]), rnd_tf32(acc[mt][nt][1]));
            *(float2*)&C[(size_t)(r + 8) * EE + c] =
                make_float2(rnd_tf32(acc[mt][nt][2]), rnd_tf32(acc[mt][nt][3]));
        }
    }
}

// ---------------------------------------------------------------------------
// Lift GEMM (BM=64): C(8192x768) = A @ B(768x768), fp32 out.
// grid (EE/BN, 8192/64) = (6,128) = 768 CTAs. Warp tile 32x32.
// ---------------------------------------------------------------------------
__global__ __launch_bounds__(256, 2) void lift_tf32_kernel(
    const float* __restrict__ A, const float* __restrict__ Bm,
    float* __restrict__ C)
{
    extern __shared__ float smx[];
    float* As = smx;
    float* Bs = smx + STAGES * 64 * LDA;

    const int tid = threadIdx.x;
    const int wid = tid >> 5, lane = tid & 31;
    const int gid = lane >> 2, tig = lane & 3;
    const int lr = lane & 7, sub = lane >> 3;
    const int warp_m = (wid >> 2) * 32;
    const int warp_n = (wid & 3) * 32;
    const int m0 = blockIdx.y * 64, n0 = blockIdx.x * BN;

    const uint32_t a_lane_off =
        (uint32_t)(((warp_m + lr + (sub & 1) * 8) * LDA + (sub >> 1) * 4) * 4);
    const uint32_t As_u = smem_u32(As);

    float acc[2][4][4] = {};

    auto load_tile = [&](int k0, int stage) {
        float* Ad = As + stage * (64 * LDA);
        float* Bd = Bs + stage * (BK * LDB);
        #pragma unroll
        for (int i = 0; i < 2; i++) {
            int f4 = tid + i * 256;
            int m = f4 >> 3, kc = (f4 & 7) * 4;
            cp_async16(&Ad[m * LDA + kc], &A[(size_t)(m0 + m) * EE + k0 + kc]);
        }
        #pragma unroll
        for (int i = 0; i < 4; i++) {
            int f4 = tid + i * 256;
            int k = f4 >> 5, nc = (f4 & 31) * 4;
            cp_async16(&Bd[k * LDB + nc], &Bm[(size_t)(k0 + k) * EE + n0 + nc]);
        }
    };

    const int ntiles = EE / BK;
    load_tile(0, 0); CP_COMMIT();
    load_tile(BK, 1); CP_COMMIT();

    for (int kt = 0; kt < ntiles; kt++) {
        CP_WAIT(1);
        __syncthreads();
        if (kt + 2 < ntiles) {
            int s = (kt + 2) % STAGES;
            load_tile((kt + 2) * BK, s);
        }
        CP_COMMIT();

        const uint32_t a_stage = As_u + (uint32_t)((kt % STAGES) * (64 * LDA) * 4) + a_lane_off;
        const float* Bd = Bs + (kt % STAGES) * (BK * LDB);
        #pragma unroll
        for (int ks = 0; ks < BK / 8; ks++) {
            const int kk = ks * 8;
            uint32_t af[2][4], bf[4][2];
            #pragma unroll
            for (int mt = 0; mt < 2; mt++)
                ldsm_x4(af[mt][0], af[mt][1], af[mt][2], af[mt][3],
                        a_stage + (uint32_t)((mt * 16 * LDA + kk) * 4));
            #pragma unroll
            for (int nt = 0; nt < 4; nt++) {
                int n = warp_n + nt * 8 + gid;
                bf[nt][0] = __float_as_uint(Bd[(kk + tig) * LDB + n]);
                bf[nt][1] = __float_as_uint(Bd[(kk + tig + 4) * LDB + n]);
            }
            #pragma unroll
            for (int mt = 0; mt < 2; mt++)
                #pragma unroll
                for (int nt = 0; nt < 4; nt++)
                    mma_tf32(acc[mt][nt], af[mt], bf[nt]);
        }
    }

    __syncthreads();
    #pragma unroll
    for (int mt = 0; mt < 2; mt++) {
        int r = m0 + warp_m + mt * 16 + gid;
        #pragma unroll
        for (int nt = 0; nt < 4; nt++) {
            int c = n0 + warp_n + nt * 8 + tig * 2;
            *(float2*)&C[(size_t)r * EE + c] =
                make_float2(acc[mt][nt][0], acc[mt][nt][1]);
            *(float2*)&C[(size_t)(r + 8) * EE + c] =
                make_float2(acc[mt][nt][2], acc[mt][nt][3]);
        }
    }
}

// ---------------------------------------------------------------------------
// QV GEMM per head (BM=64): QVcat(1024x512) = Q_h @ Vcat(1024x512)
//   Vcat[k][n] = g_V[((n>>6)*SS + k)*EE + h*PP + (n&63)]
// grid (4, 16, 12) = 768 CTAs.
// ---------------------------------------------------------------------------
__global__ __launch_bounds__(256, 2) void qv_tf32_kernel()
{
    extern __shared__ float smx[];
    float* As = smx;
    float* Bs = smx + STAGES * 64 * LDA;

    const int h = blockIdx.z;
    const int tid = threadIdx.x;
    const int wid = tid >> 5, lane = tid & 31;
    const int gid = lane >> 2, tig = lane & 3;
    const int lr = lane & 7, sub = lane >> 3;
    const int warp_m = (wid >> 2) * 32;
    const int warp_n = (wid & 3) * 32;
    const int m0 = blockIdx.y * 64, n0 = blockIdx.x * BN;

    const float* A  = g_Qt + (size_t)h * SS * SS;
    const float* Vb = g_V + h * PP;

    const uint32_t a_lane_off =
        (uint32_t)(((warp_m + lr + (sub & 1) * 8) * LDA + (sub >> 1) * 4) * 4);
    const uint32_t As_u = smem_u32(As);

    float acc[2][4][4] = {};

    auto load_tile = [&](int k0, int stage) {
        float* Ad = As + stage * (64 * LDA);
        float* Bd = Bs + stage * (BK * LDB);
        #pragma unroll
        for (int i = 0; i < 2; i++) {
            int f4 = tid + i * 256;
            int m = f4 >> 3, kc = (f4 & 7) * 4;
            cp_async16(&Ad[m * LDA + kc], &A[(size_t)(m0 + m) * SS + k0 + kc]);
        }
        #pragma unroll
        for (int i = 0; i < 4; i++) {
            int f4 = tid + i * 256;
            int k = f4 >> 5, nc = (f4 & 31) * 4;
            int n = n0 + nc;
            cp_async16(&Bd[k * LDB + nc],
                       &Vb[(size_t)((n >> 6) * SS + k0 + k) * EE + (n & 63)]);
        }
    };

    const int ntiles = SS / BK;
    load_tile(0, 0); CP_COMMIT();
    load_tile(BK, 1); CP_COMMIT();

    for (int kt = 0; kt < ntiles; kt++) {
        CP_WAIT(1);
        __syncthreads();
        if (kt + 2 < ntiles) {
            int s = (kt + 2) % STAGES;
            load_tile((kt + 2) * BK, s);
        }
        CP_COMMIT();

        const uint32_t a_stage = As_u + (uint32_t)((kt % STAGES) * (64 * LDA) * 4) + a_lane_off;
        const float* Bd = Bs + (kt % STAGES) * (BK * LDB);
        #pragma unroll
        for (int ks = 0; ks < BK / 8; ks++) {
            const int kk = ks * 8;
            uint32_t af[2][4], bf[4][2];
            #pragma unroll
            for (int mt = 0; mt < 2; mt++)
                ldsm_x4(af[mt][0], af[mt][1], af[mt][2], af[mt][3],
                        a_stage + (uint32_t)((mt * 16 * LDA + kk) * 4));
            #pragma unroll
            for (int nt = 0; nt < 4; nt++) {
                int n = warp_n + nt * 8 + gid;
                bf[nt][0] = __float_as_uint(Bd[(kk + tig) * LDB + n]);
                bf[nt][1] = __float_as_uint(Bd[(kk + tig + 4) * LDB + n]);
            }
            #pragma unroll
            for (int mt = 0; mt < 2; mt++)
                #pragma unroll
                for (int nt = 0; nt < 4; nt++)
                    mma_tf32(acc[mt][nt], af[mt], bf[nt]);
        }
    }

    __syncthreads();
    float* QVb = g_QV + h * PP;
    #pragma unroll
    for (int mt = 0; mt < 2; mt++) {
        int r = m0 + warp_m + mt * 16 + gid;
        #pragma unroll
        for (int nt = 0; nt < 4; nt++) {
            int n = n0 + warp_n + nt * 8 + tig * 2;
            int b_ = n >> 6, p = n & 63;
            *(float2*)&QVb[(size_t)(b_ * SS + r) * EE + p] =
                make_float2(rnd_tf32(acc[mt][nt][0]), rnd_tf32(acc[mt][nt][1]));
            *(float2*)&QVb[(size_t)(b_ * SS + r + 8) * EE + p] =
                make_float2(rnd_tf32(acc[mt][nt][2]), rnd_tf32(acc[mt][nt][3]));
        }
    }
}

// ---------------------------------------------------------------------------
// Tensor-core causal attention (race-fixed schedule; LDSM fragments).
// ---------------------------------------------------------------------------
#define ALDK 68
#define ALDV 72
#define ATT_SMEM ((128*ALDK + 64*ALDK + 64*ALDV + 128*ALDK + 128*4) * 4)

__global__ __launch_bounds__(256, 2) void attn_mma_kernel()
{
    extern __shared__ float sm[];
    float* ks  = sm;                       // 128 x 68
    float* qs  = ks + 128 * ALDK;          // 64 x 68
    float* vs  = qs + 64 * ALDK;           // 64 x 72
    float* ps  = vs + 64 * ALDV;           // 128 x 68
    float* lsm = ps + 128 * ALDK;          // 128 x 4

    const int it = 7 - (int)blockIdx.x;    // heavy blocks first
    const int h = blockIdx.y, b = blockIdx.z;
    const int i0 = it * 128;
    const int tid = threadIdx.x;
    const int wid = tid >> 5, lane = tid & 31;
    const int gid = lane >> 2, tig = lane & 3;
    const int lr = lane & 7, sub = lane >> 3;
    const int wm = wid >> 2, wn = wid & 3;
    const int rbase = wm * 64;
    const int cbase = wn * 16;
    const float scale = 0.03608439182435161f;  // 1/sqrt(768)

    // LDSM per-lane bases:
    //   A-pattern ([row][k]): row = lr + (sub&1)*8, col += (sub>>1)*4
    //   B-pattern ([n][k], both nt in one x4): row = lr + (sub>>1)*8, col += (sub&1)*4
    const uint32_t ksf = smem_u32(ks) +
        (uint32_t)(((rbase + lr + (sub & 1) * 8) * ALDK + (sub >> 1) * 4) * 4);
    const uint32_t qsf = smem_u32(qs) +
        (uint32_t)(((cbase + lr + (sub >> 1) * 8) * ALDK + (sub & 1) * 4) * 4);
    const uint32_t psf = smem_u32(ps) +
        (uint32_t)(((rbase + lr + (sub & 1) * 8) * ALDK + (sub >> 1) * 4) * 4);

    const float* Kb  = g_K  + (size_t)b * SS * EE + h * PP;
    const float* QVb = g_QV + (size_t)b * SS * EE + h * PP;
    const float* Vb  = g_V  + (size_t)b * SS * EE + h * PP;

    #pragma unroll
    for (int t = 0; t < 8; t++) {
        int idx = tid + t * 256;
        int r = idx >> 4, c4 = (idx & 15) * 4;
        cp_async16(&ks[r * ALDK + c4], &Kb[(size_t)(i0 + r) * EE + c4]);
    }
    CP_COMMIT();

    #pragma unroll
    for (int t = 0; t < 4; t++) {
        int idx = tid + t * 256;
        int r = idx >> 4, c4 = (idx & 15) * 4;
        cp_async16(&qs[r * ALDK + c4], &QVb[(size_t)r * EE + c4]);
    }
    CP_COMMIT();

    float Oa[4][2][4] = {};
    float lacc[4][2] = {};

    const int njt = 2 * it + 2;
    for (int jt = 0; jt < njt; jt++) {
        const int j0 = jt * 64;

        CP_WAIT(0);          // qs(jt) (and ks on jt=0) arrived
        __syncthreads();     // all warps done with PV(jt-1) -> vs/ps writable

        #pragma unroll
        for (int t = 0; t < 4; t++) {
            int idx = tid + t * 256;
            int r = idx >> 4, c4 = (idx & 15) * 4;
            cp_async16(&vs[r * ALDV + c4], &Vb[(size_t)(j0 + r) * EE + c4]);
        }
        CP_COMMIT();

        // ---- S = K @ QV^T  (M=128 i, N=64 j, K=64 p)
        float Sa[4][2][4] = {};
        #pragma unroll
        for (int kss = 0; kss < 8; kss++) {
            const int kk = kss * 8;
            uint32_t af[4][4], bf[2][2];
            #pragma unroll
            for (int mt = 0; mt < 4; mt++)
                ldsm_x4(af[mt][0], af[mt][1], af[mt][2], af[mt][3],
                        ksf + (uint32_t)((mt * 16 * ALDK + kk) * 4));
            ldsm_x4(bf[0][0], bf[0][1], bf[1][0], bf[1][1],
                    qsf + (uint32_t)(kk * 4));
            #pragma unroll
            for (int mt = 0; mt < 4; mt++)
                #pragma unroll
                for (int nt = 0; nt < 2; nt++)
                    mma_tf32(Sa[mt][nt], af[mt], bf[nt]);
        }

        // ---- mask + exp, write P tile (tf32), accumulate row sums
        const bool need_mask = (jt >= 2 * it);
        #pragma unroll
        for (int mt = 0; mt < 4; mt++) {
            #pragma unroll
            for (int nt = 0; nt < 2; nt++) {
                int rr0 = rbase + mt * 16 + gid;
                int cc = cbase + nt * 8 + 2 * tig;
                int iglob0 = i0 + rr0, iglob1 = iglob0 + 8;
                int jg = j0 + cc;
                float e0 = __expf(Sa[mt][nt][0] * scale);
                float e1 = __expf(Sa[mt][nt][1] * scale);
                float e2 = __expf(Sa[mt][nt][2] * scale);
                float e3 = __expf(Sa[mt][nt][3] * scale);
                if (need_mask) {
                    if (jg     > iglob0) e0 = 0.0f;
                    if (jg + 1 > iglob0) e1 = 0.0f;
                    if (jg     > iglob1) e2 = 0.0f;
                    if (jg + 1 > iglob1) e3 = 0.0f;
                }
                lacc[mt][0] += e0 + e1;
                lacc[mt][1] += e2 + e3;
                *(float2*)&ps[rr0 * ALDK + cc] =
                    make_float2(rnd_tf32(e0), rnd_tf32(e1));
                *(float2*)&ps[(rr0 + 8) * ALDK + cc] =
                    make_float2(rnd_tf32(e2), rnd_tf32(e3));
            }
        }
        CP_WAIT(0);          // vs(jt) arrived (hidden behind S-mma + exp)
        __syncthreads();     // P tile complete, vs visible

        // ---- O += P @ V  (M=128 i, N=64 p, K=64 j)
        #pragma unroll
        for (int kss = 0; kss < 8; kss++) {
            const int kk = kss * 8;
            uint32_t af[4][4], bf[2][2];
            #pragma unroll
            for (int mt = 0; mt < 4; mt++)
                ldsm_x4(af[mt][0], af[mt][1], af[mt][2], af[mt][3],
                        psf + (uint32_t)((mt * 16 * ALDK + kk) * 4));
            #pragma unroll
            for (int nt = 0; nt < 2; nt++) {
                int n = cbase + nt * 8 + gid;
                bf[nt][0] = __float_as_uint(vs[(kk + tig) * ALDV + n]);
                bf[nt][1] = __float_as_uint(vs[(kk + tig + 4) * ALDV + n]);
            }
            #pragma unroll
            for (int mt = 0; mt < 4; mt++)
                #pragma unroll
                for (int nt = 0; nt < 2; nt++)
                    mma_tf32(Oa[mt][nt], af[mt], bf[nt]);
        }

        if (jt + 1 < njt) {
            const int jn = (jt + 1) * 64;
            #pragma unroll
            for (int t = 0; t < 4; t++) {
                int idx = tid + t * 256;
                int r = idx >> 4, c4 = (idx & 15) * 4;
                cp_async16(&qs[r * ALDK + c4], &QVb[(size_t)(jn + r) * EE + c4]);
            }
        }
        CP_COMMIT();
    }

    #pragma unroll
    for (int mt = 0; mt < 4; mt++) {
        #pragma unroll
        for (int rr = 0; rr < 2; rr++) {
            float v = lacc[mt][rr];
            v += __shfl_xor_sync(0xffffffffu, v, 1);
            v += __shfl_xor_sync(0xffffffffu, v, 2);
            lacc[mt][rr] = v;
        }
    }
    __syncthreads();
    if (tig == 0) {
        #pragma unroll
        for (int mt = 0; mt < 4; mt++) {
            int r = rbase + mt * 16 + gid;
            lsm[r * 4 + wn] = lacc[mt][0];
            lsm[(r + 8) * 4 + wn] = lacc[mt][1];
        }
    }
    __syncthreads();

    float* Ab = g_At + (size_t)b * SS * EE + h * PP;
    #pragma unroll
    for (int mt = 0; mt < 4; mt++) {
        int r = rbase + mt * 16 + gid;
        float inv0 = 1.0f / (lsm[r * 4] + lsm[r * 4 + 1] + lsm[r * 4 + 2] + lsm[r * 4 + 3]);
        int r8 = r + 8;
        float inv1 = 1.0f / (lsm[r8 * 4] + lsm[r8 * 4 + 1] + lsm[r8 * 4 + 2] + lsm[r8 * 4 + 3]);
        #pragma unroll
        for (int nt = 0; nt < 2; nt++) {
            int c = cbase + nt * 8 + 2 * tig;
            *(float2*)&Ab[(size_t)(i0 + r) * EE + c] =
                make_float2(rnd_tf32(Oa[mt][nt][0] * inv0), rnd_tf32(Oa[mt][nt][1] * inv0));
            *(float2*)&Ab[(size_t)(i0 + r8) * EE + c] =
                make_float2(rnd_tf32(Oa[mt][nt][2] * inv1), rnd_tf32(Oa[mt][nt][3] * inv1));
        }
    }
}

// ---------------------------------------------------------------------------
extern "C" void kernel_launch(void* const* d_in, const int* in_sizes, int n_in,
                              void* d_out, int out_size)
{
    const float* x    = (const float*)d_in[0];
    const float* wk   = (const float*)d_in[1];
    const float* wv   = (const float*)d_in[2];
    const float* q    = (const float*)d_in[3];
    const float* lift = (const float*)d_in[4];
    float* out = (float*)d_out;

    static bool attr_done = false;
    if (!attr_done) {
        cudaFuncSetAttribute(proj_tf32_kernel,
            cudaFuncAttributeMaxDynamicSharedMemorySize, GEMM_SMEM128);
        cudaFuncSetAttribute(lift_tf32_kernel,
            cudaFuncAttributeMaxDynamicSharedMemorySize, GEMM_SMEM64);
        cudaFuncSetAttribute(qv_tf32_kernel,
            cudaFuncAttributeMaxDynamicSharedMemorySize, GEMM_SMEM64);
        cudaFuncSetAttribute(attn_mma_kernel,
            cudaFuncAttributeMaxDynamicSharedMemorySize, ATT_SMEM);
        attr_done = true;
    }

    float *gK, *gV, *gAt, *gXt, *gQt, *gWkt, *gWvt, *gLtt;
    cudaGetSymbolAddress((void**)&gK,  g_K);
    cudaGetSymbolAddress((void**)&gV,  g_V);
    cudaGetSymbolAddress((void**)&gAt, g_At);
    cudaGetSymbolAddress((void**)&gXt, g_Xt);
    cudaGetSymbolAddress((void**)&gQt, g_Qt);
    cudaGetSymbolAddress((void**)&gWkt, g_Wkt);
    cudaGetSymbolAddress((void**)&gWvt, g_Wvt);
    cudaGetSymbolAddress((void**)&gLtt, g_Ltt);

    // --- prepass: ONE segmented tf32-rounding sweep
    round_all_kernel<<<(N4_TOT + 255) / 256, 256>>>(
        (const float4*)x, (const float4*)q, (const float4*)wk,
        (const float4*)wv, (const float4*)lift,
        (float4*)gXt, (float4*)gQt, (float4*)gWkt,
        (float4*)gWvt, (float4*)gLtt);

    const int M = BB * SS;

    // --- fused K/V projections (768 CTAs)
    dim3 gp(EE / BN, M / 128, 2);
    proj_tf32_kernel<<<gp, 256, GEMM_SMEM128>>>(gXt, gWkt, gWvt, gK, gV);

    // --- QV = Q_h @ Vcat per head (768 CTAs)
    dim3 gq((BB * PP) / BN, SS / 64, HH);
    qv_tf32_kernel<<<gq, 256, GEMM_SMEM64>>>();

    // --- causal attention (tensor core)
    dim3 ga(SS / 128, HH, BB);
    attn_mma_kernel<<<ga, 256, ATT_SMEM>>>();

    // --- out = attn @ lifting (768 CTAs, fp32 output)
    dim3 gl(EE / BN, M / 64);
    lift_tf32_kernel<<<gl, 256, GEMM_SMEM64>>>(gAt, gLtt, out);
}

// round 10
// speedup vs baseline: 4.8247x; 1.0132x over previous
#include <cuda_runtime.h>
#include <cuda_bf16.h>
#include <cstdint>

#define BB 8
#define SS 1024
#define EE 768
#define HH 12
#define PP 64

// ---------------------------------------------------------------------------
// Scratch (__device__ globals; allocation-free rule)
// ---------------------------------------------------------------------------
__device__ float g_K  [BB*SS*EE];   // tf32-rounded, [b][s][h][p]
__device__ float g_V  [BB*SS*EE];   // tf32-rounded
__device__ float g_QV [BB*SS*EE];   // tf32-rounded
__device__ float g_At [BB*SS*EE];   // tf32-rounded
__device__ float g_Xt [BB*SS*EE];   // tf32-rounded copy of x
__device__ float g_Qt [HH*SS*SS];   // tf32-rounded copy of q_heads
__device__ float g_Wkt[HH*EE*PP];
__device__ float g_Wvt[HH*EE*PP];
__device__ float g_Ltt[EE*EE];

// ---------------------------------------------------------------------------
// helpers
// ---------------------------------------------------------------------------
__device__ __forceinline__ uint32_t f2tf32(float f) {
    uint32_t u;
    asm("cvt.rna.tf32.f32 %0, %1;" : "=r"(u) : "f"(f));
    return u;
}
__device__ __forceinline__ float rnd_tf32(float f) {
    return __uint_as_float(f2tf32(f));
}
__device__ __forceinline__ void mma_tf32(float c[4], const uint32_t a[4],
                                         const uint32_t b[2]) {
    asm volatile(
        "mma.sync.aligned.m16n8k8.row.col.f32.tf32.tf32.f32 "
        "{%0,%1,%2,%3}, {%4,%5,%6,%7}, {%8,%9}, {%0,%1,%2,%3};"
        : "+f"(c[0]), "+f"(c[1]), "+f"(c[2]), "+f"(c[3])
        : "r"(a[0]), "r"(a[1]), "r"(a[2]), "r"(a[3]), "r"(b[0]), "r"(b[1]));
}
__device__ __forceinline__ void cp_async16(void* sptr, const void* gptr) {
    uint32_t s = (uint32_t)__cvta_generic_to_shared(sptr);
    asm volatile("cp.async.cg.shared.global [%0], [%1], 16;\n"
                 :: "r"(s), "l"(gptr) : "memory");
}
#define CP_COMMIT() asm volatile("cp.async.commit_group;\n" ::: "memory")
#define CP_WAIT(n)  asm volatile("cp.async.wait_group %0;\n" :: "n"(n) : "memory")

__device__ __forceinline__ uint32_t smem_u32(const void* p) {
    return (uint32_t)__cvta_generic_to_shared(p);
}
// tf32 fragment loader: 4 8x4-tf32 submatrices (viewed as 8x8 b16 each).
__device__ __forceinline__ void ldsm_x4(uint32_t& r0, uint32_t& r1,
                                        uint32_t& r2, uint32_t& r3, uint32_t a) {
    asm volatile("ldmatrix.sync.aligned.m8n8.x4.shared.b16 {%0,%1,%2,%3}, [%4];"
                 : "=r"(r0), "=r"(r1), "=r"(r2), "=r"(r3) : "r"(a));
}

// ---------------------------------------------------------------------------
// Prepass: ONE segmented tf32-rounding sweep over all five inputs
// ---------------------------------------------------------------------------
#define N4_X  ((BB*SS*EE)/4)
#define N4_Q  ((HH*SS*SS)/4)
#define N4_W  ((HH*EE*PP)/4)
#define N4_L  ((EE*EE)/4)
#define N4_TOT (N4_X + N4_Q + 2*N4_W + N4_L)

__global__ void round_all_kernel(
    const float4* __restrict__ x,  const float4* __restrict__ q,
    const float4* __restrict__ wk, const float4* __restrict__ wv,
    const float4* __restrict__ lf,
    float4* __restrict__ ox,  float4* __restrict__ oq,
    float4* __restrict__ owk, float4* __restrict__ owv,
    float4* __restrict__ olf)
{
    int i = blockIdx.x * blockDim.x + threadIdx.x;
    const float4* src; float4* dst; int li;
    if (i < N4_X) { src = x; dst = ox; li = i; }
    else if (i < N4_X + N4_Q) { src = q; dst = oq; li = i - N4_X; }
    else if (i < N4_X + N4_Q + N4_W) { src = wk; dst = owk; li = i - N4_X - N4_Q; }
    else if (i < N4_X + N4_Q + 2*N4_W) { src = wv; dst = owv; li = i - N4_X - N4_Q - N4_W; }
    else if (i < N4_TOT) { src = lf; dst = olf; li = i - N4_X - N4_Q - 2*N4_W; }
    else return;
    float4 v = src[li];
    v.x = rnd_tf32(v.x); v.y = rnd_tf32(v.y);
    v.z = rnd_tf32(v.z); v.w = rnd_tf32(v.w);
    dst[li] = v;
}

// ---------------------------------------------------------------------------
// GEMM geometry: BM=64, BN=128, BK=32, 2 stages, 3 CTAs/SM.
// Warp tile 32x32 (8 warps: wm 2 x wn 4). Double-sync 2-stage pipeline
// (R4-verified schedule).
// ---------------------------------------------------------------------------
#define BM 64
#define BN 128
#define BK 32
#define LDA 36
#define LDB 136
#define STAGES 2
#define GEMM_SMEM ((STAGES*(BM*LDA + BK*LDB)) * 4)

// ---------------------------------------------------------------------------
// Fused K/V projection: blockIdx.z selects (Wk->g_K)/(Wv->g_V).
// B head-packed: B[k][n] = w[(n>>6)*EE*64 + k*64 + (n&63)]. tf32-rounded out.
// grid (EE/BN, 8192/BM, 2), 256 threads.
// ---------------------------------------------------------------------------
__global__ __launch_bounds__(256, 3) void proj_tf32_kernel(
    const float* __restrict__ A,
    const float* __restrict__ Bk, const float* __restrict__ Bv,
    float* __restrict__ Ck, float* __restrict__ Cv)
{
    extern __shared__ float smx[];
    float* As = smx;
    float* Bs = smx + STAGES * BM * LDA;

    const float* Bm = blockIdx.z ? Bv : Bk;
    float* C = blockIdx.z ? Cv : Ck;

    const int tid = threadIdx.x;
    const int wid = tid >> 5, lane = tid & 31;
    const int gid = lane >> 2, tig = lane & 3;
    const int lr = lane & 7, sub = lane >> 3;
    const int warp_m = (wid >> 2) * 32;
    const int warp_n = (wid & 3) * 32;
    const int m0 = blockIdx.y * BM, n0 = blockIdx.x * BN;

    const uint32_t a_lane_off =
        (uint32_t)(((warp_m + lr + (sub & 1) * 8) * LDA + (sub >> 1) * 4) * 4);
    const uint32_t As_u = smem_u32(As);

    float acc[2][4][4] = {};

    auto load_tile = [&](int k0, int stage) {
        float* Ad = As + stage * (BM * LDA);
        float* Bd = Bs + stage * (BK * LDB);
        #pragma unroll
        for (int i = 0; i < 2; i++) {
            int f4 = tid + i * 256;
            int m = f4 >> 3, kc = (f4 & 7) * 4;
            cp_async16(&Ad[m * LDA + kc], &A[(size_t)(m0 + m) * EE + k0 + kc]);
        }
        #pragma unroll
        for (int i = 0; i < 4; i++) {
            int f4 = tid + i * 256;
            int k = f4 >> 5, nc = (f4 & 31) * 4;
            int n = n0 + nc;
            cp_async16(&Bd[k * LDB + nc],
                       &Bm[(size_t)(n >> 6) * (EE * 64) + (k0 + k) * 64 + (n & 63)]);
        }
    };

    const int ntiles = EE / BK;
    load_tile(0, 0); CP_COMMIT();

    for (int kt = 0; kt < ntiles; kt++) {
        if (kt + 1 < ntiles) {
            load_tile((kt + 1) * BK, (kt + 1) & 1);
            CP_COMMIT();
            CP_WAIT(1);
        } else {
            CP_WAIT(0);
        }
        __syncthreads();

        const uint32_t a_stage = As_u + (uint32_t)((kt & 1) * (BM * LDA) * 4) + a_lane_off;
        const float* Bd = Bs + (kt & 1) * (BK * LDB);
        #pragma unroll
        for (int ks = 0; ks < BK / 8; ks++) {
            const int kk = ks * 8;
            uint32_t af[2][4], bf[4][2];
            #pragma unroll
            for (int mt = 0; mt < 2; mt++)
                ldsm_x4(af[mt][0], af[mt][1], af[mt][2], af[mt][3],
                        a_stage + (uint32_t)((mt * 16 * LDA + kk) * 4));
            #pragma unroll
            for (int nt = 0; nt < 4; nt++) {
                int n = warp_n + nt * 8 + gid;
                bf[nt][0] = __float_as_uint(Bd[(kk + tig) * LDB + n]);
                bf[nt][1] = __float_as_uint(Bd[(kk + tig + 4) * LDB + n]);
            }
            #pragma unroll
            for (int mt = 0; mt < 2; mt++)
                #pragma unroll
                for (int nt = 0; nt < 4; nt++)
                    mma_tf32(acc[mt][nt], af[mt], bf[nt]);
        }
        __syncthreads();
    }

    #pragma unroll
    for (int mt = 0; mt < 2; mt++) {
        int r = m0 + warp_m + mt * 16 + gid;
        #pragma unroll
        for (int nt = 0; nt < 4; nt++) {
            int c = n0 + warp_n + nt * 8 + tig * 2;
            *(float2*)&C[(size_t)r * EE + c] =
                make_float2(rnd_tf32(acc[mt][nt][0]), rnd_tf32(acc[mt][nt][1]));
            *(float2*)&C[(size_t)(r + 8) * EE + c] =
                make_float2(rnd_tf32(acc[mt][nt][2]), rnd_tf32(acc[mt][nt][3]));
        }
    }
}

// ---------------------------------------------------------------------------
// Lift GEMM: C(8192x768) = A @ B(768x768), fp32 out. grid (6, 128).
// ---------------------------------------------------------------------------
__global__ __launch_bounds__(256, 3) void lift_tf32_kernel(
    const float* __restrict__ A, const float* __restrict__ Bm,
    float* __restrict__ C)
{
    extern __shared__ float smx[];
    float* As = smx;
    float* Bs = smx + STAGES * BM * LDA;

    const int tid = threadIdx.x;
    const int wid = tid >> 5, lane = tid & 31;
    const int gid = lane >> 2, tig = lane & 3;
    const int lr = lane & 7, sub = lane >> 3;
    const int warp_m = (wid >> 2) * 32;
    const int warp_n = (wid & 3) * 32;
    const int m0 = blockIdx.y * BM, n0 = blockIdx.x * BN;

    const uint32_t a_lane_off =
        (uint32_t)(((warp_m + lr + (sub & 1) * 8) * LDA + (sub >> 1) * 4) * 4);
    const uint32_t As_u = smem_u32(As);

    float acc[2][4][4] = {};

    auto load_tile = [&](int k0, int stage) {
        float* Ad = As + stage * (BM * LDA);
        float* Bd = Bs + stage * (BK * LDB);
        #pragma unroll
        for (int i = 0; i < 2; i++) {
            int f4 = tid + i * 256;
            int m = f4 >> 3, kc = (f4 & 7) * 4;
            cp_async16(&Ad[m * LDA + kc], &A[(size_t)(m0 + m) * EE + k0 + kc]);
        }
        #pragma unroll
        for (int i = 0; i < 4; i++) {
            int f4 = tid + i * 256;
            int k = f4 >> 5, nc = (f4 & 31) * 4;
            cp_async16(&Bd[k * LDB + nc], &Bm[(size_t)(k0 + k) * EE + n0 + nc]);
        }
    };

    const int ntiles = EE / BK;
    load_tile(0, 0); CP_COMMIT();

    for (int kt = 0; kt < ntiles; kt++) {
        if (kt + 1 < ntiles) {
            load_tile((kt + 1) * BK, (kt + 1) & 1);
            CP_COMMIT();
            CP_WAIT(1);
        } else {
            CP_WAIT(0);
        }
        __syncthreads();

        const uint32_t a_stage = As_u + (uint32_t)((kt & 1) * (BM * LDA) * 4) + a_lane_off;
        const float* Bd = Bs + (kt & 1) * (BK * LDB);
        #pragma unroll
        for (int ks = 0; ks < BK / 8; ks++) {
            const int kk = ks * 8;
            uint32_t af[2][4], bf[4][2];
            #pragma unroll
            for (int mt = 0; mt < 2; mt++)
                ldsm_x4(af[mt][0], af[mt][1], af[mt][2], af[mt][3],
                        a_stage + (uint32_t)((mt * 16 * LDA + kk) * 4));
            #pragma unroll
            for (int nt = 0; nt < 4; nt++) {
                int n = warp_n + nt * 8 + gid;
                bf[nt][0] = __float_as_uint(Bd[(kk + tig) * LDB + n]);
                bf[nt][1] = __float_as_uint(Bd[(kk + tig + 4) * LDB + n]);
            }
            #pragma unroll
            for (int mt = 0; mt < 2; mt++)
                #pragma unroll
                for (int nt = 0; nt < 4; nt++)
                    mma_tf32(acc[mt][nt], af[mt], bf[nt]);
        }
        __syncthreads();
    }

    #pragma unroll
    for (int mt = 0; mt < 2; mt++) {
        int r = m0 + warp_m + mt * 16 + gid;
        #pragma unroll
        for (int nt = 0; nt < 4; nt++) {
            int c = n0 + warp_n + nt * 8 + tig * 2;
            *(float2*)&C[(size_t)r * EE + c] =
                make_float2(acc[mt][nt][0], acc[mt][nt][1]);
            *(float2*)&C[(size_t)(r + 8) * EE + c] =
                make_float2(acc[mt][nt][2], acc[mt][nt][3]);
        }
    }
}

// ---------------------------------------------------------------------------
// QV GEMM per head: QVcat(1024x512) = Q_h @ Vcat(1024x512)
//   Vcat[k][n] = g_V[((n>>6)*SS + k)*EE + h*PP + (n&63)]
// grid (4, 16, 12).
// ---------------------------------------------------------------------------
__global__ __launch_bounds__(256, 3) void qv_tf32_kernel()
{
    extern __shared__ float smx[];
    float* As = smx;
    float* Bs = smx + STAGES * BM * LDA;

    const int h = blockIdx.z;
    const int tid = threadIdx.x;
    const int wid = tid >> 5, lane = tid & 31;
    const int gid = lane >> 2, tig = lane & 3;
    const int lr = lane & 7, sub = lane >> 3;
    const int warp_m = (wid >> 2) * 32;
    const int warp_n = (wid & 3) * 32;
    const int m0 = blockIdx.y * BM, n0 = blockIdx.x * BN;

    const float* A  = g_Qt + (size_t)h * SS * SS;
    const float* Vb = g_V + h * PP;

    const uint32_t a_lane_off =
        (uint32_t)(((warp_m + lr + (sub & 1) * 8) * LDA + (sub >> 1) * 4) * 4);
    const uint32_t As_u = smem_u32(As);

    float acc[2][4][4] = {};

    auto load_tile = [&](int k0, int stage) {
        float* Ad = As + stage * (BM * LDA);
        float* Bd = Bs + stage * (BK * LDB);
        #pragma unroll
        for (int i = 0; i < 2; i++) {
            int f4 = tid + i * 256;
            int m = f4 >> 3, kc = (f4 & 7) * 4;
            cp_async16(&Ad[m * LDA + kc], &A[(size_t)(m0 + m) * SS + k0 + kc]);
        }
        #pragma unroll
        for (int i = 0; i < 4; i++) {
            int f4 = tid + i * 256;
            int k = f4 >> 5, nc = (f4 & 31) * 4;
            int n = n0 + nc;
            cp_async16(&Bd[k * LDB + nc],
                       &Vb[(size_t)((n >> 6) * SS + k0 + k) * EE + (n & 63)]);
        }
    };

    const int ntiles = SS / BK;
    load_tile(0, 0); CP_COMMIT();

    for (int kt = 0; kt < ntiles; kt++) {
        if (kt + 1 < ntiles) {
            load_tile((kt + 1) * BK, (kt + 1) & 1);
            CP_COMMIT();
            CP_WAIT(1);
        } else {
            CP_WAIT(0);
        }
        __syncthreads();

        const uint32_t a_stage = As_u + (uint32_t)((kt & 1) * (BM * LDA) * 4) + a_lane_off;
        const float* Bd = Bs + (kt & 1) * (BK * LDB);
        #pragma unroll
        for (int ks = 0; ks < BK / 8; ks++) {
            const int kk = ks * 8;
            uint32_t af[2][4], bf[4][2];
            #pragma unroll
            for (int mt = 0; mt < 2; mt++)
                ldsm_x4(af[mt][0], af[mt][1], af[mt][2], af[mt][3],
                        a_stage + (uint32_t)((mt * 16 * LDA + kk) * 4));
            #pragma unroll
            for (int nt = 0; nt < 4; nt++) {
                int n = warp_n + nt * 8 + gid;
                bf[nt][0] = __float_as_uint(Bd[(kk + tig) * LDB + n]);
                bf[nt][1] = __float_as_uint(Bd[(kk + tig + 4) * LDB + n]);
            }
            #pragma unroll
            for (int mt = 0; mt < 2; mt++)
                #pragma unroll
                for (int nt = 0; nt < 4; nt++)
                    mma_tf32(acc[mt][nt], af[mt], bf[nt]);
        }
        __syncthreads();
    }

    float* QVb = g_QV + h * PP;
    #pragma unroll
    for (int mt = 0; mt < 2; mt++) {
        int r = m0 + warp_m + mt * 16 + gid;
        #pragma unroll
        for (int nt = 0; nt < 4; nt++) {
            int n = n0 + warp_n + nt * 8 + tig * 2;
            int b_ = n >> 6, p = n & 63;
            *(float2*)&QVb[(size_t)(b_ * SS + r) * EE + p] =
                make_float2(rnd_tf32(acc[mt][nt][0]), rnd_tf32(acc[mt][nt][1]));
            *(float2*)&QVb[(size_t)(b_ * SS + r + 8) * EE + p] =
                make_float2(rnd_tf32(acc[mt][nt][2]), rnd_tf32(acc[mt][nt][3]));
        }
    }
}

// ---------------------------------------------------------------------------
// Tensor-core causal attention (race-fixed schedule; LDSM fragments).
// Unchanged from R8 (verified).
// ---------------------------------------------------------------------------
#define ALDK 68
#define ALDV 72
#define ATT_SMEM ((128*ALDK + 64*ALDK + 64*ALDV + 128*ALDK + 128*4) * 4)

__global__ __launch_bounds__(256, 2) void attn_mma_kernel()
{
    extern __shared__ float sm[];
    float* ks  = sm;                       // 128 x 68
    float* qs  = ks + 128 * ALDK;          // 64 x 68
    float* vs  = qs + 64 * ALDK;           // 64 x 72
    float* ps  = vs + 64 * ALDV;           // 128 x 68
    float* lsm = ps + 128 * ALDK;          // 128 x 4

    const int it = 7 - (int)blockIdx.x;    // heavy blocks first
    const int h = blockIdx.y, b = blockIdx.z;
    const int i0 = it * 128;
    const int tid = threadIdx.x;
    const int wid = tid >> 5, lane = tid & 31;
    const int gid = lane >> 2, tig = lane & 3;
    const int lr = lane & 7, sub = lane >> 3;
    const int wm = wid >> 2, wn = wid & 3;
    const int rbase = wm * 64;
    const int cbase = wn * 16;
    const float scale = 0.03608439182435161f;  // 1/sqrt(768)

    const uint32_t ksf = smem_u32(ks) +
        (uint32_t)(((rbase + lr + (sub & 1) * 8) * ALDK + (sub >> 1) * 4) * 4);
    const uint32_t qsf = smem_u32(qs) +
        (uint32_t)(((cbase + lr + (sub >> 1) * 8) * ALDK + (sub & 1) * 4) * 4);
    const uint32_t psf = smem_u32(ps) +
        (uint32_t)(((rbase + lr + (sub & 1) * 8) * ALDK + (sub >> 1) * 4) * 4);

    const float* Kb  = g_K  + (size_t)b * SS * EE + h * PP;
    const float* QVb = g_QV + (size_t)b * SS * EE + h * PP;
    const float* Vb  = g_V  + (size_t)b * SS * EE + h * PP;

    #pragma unroll
    for (int t = 0; t < 8; t++) {
        int idx = tid + t * 256;
        int r = idx >> 4, c4 = (idx & 15) * 4;
        cp_async16(&ks[r * ALDK + c4], &Kb[(size_t)(i0 + r) * EE + c4]);
    }
    CP_COMMIT();

    #pragma unroll
    for (int t = 0; t < 4; t++) {
        int idx = tid + t * 256;
        int r = idx >> 4, c4 = (idx & 15) * 4;
        cp_async16(&qs[r * ALDK + c4], &QVb[(size_t)r * EE + c4]);
    }
    CP_COMMIT();

    float Oa[4][2][4] = {};
    float lacc[4][2] = {};

    const int njt = 2 * it + 2;
    for (int jt = 0; jt < njt; jt++) {
        const int j0 = jt * 64;

        CP_WAIT(0);          // qs(jt) (and ks on jt=0) arrived
        __syncthreads();     // all warps done with PV(jt-1) -> vs/ps writable

        #pragma unroll
        for (int t = 0; t < 4; t++) {
            int idx = tid + t * 256;
            int r = idx >> 4, c4 = (idx & 15) * 4;
            cp_async16(&vs[r * ALDV + c4], &Vb[(size_t)(j0 + r) * EE + c4]);
        }
        CP_COMMIT();

        // ---- S = K @ QV^T  (M=128 i, N=64 j, K=64 p)
        float Sa[4][2][4] = {};
        #pragma unroll
        for (int kss = 0; kss < 8; kss++) {
            const int kk = kss * 8;
            uint32_t af[4][4], bf[2][2];
            #pragma unroll
            for (int mt = 0; mt < 4; mt++)
                ldsm_x4(af[mt][0], af[mt][1], af[mt][2], af[mt][3],
                        ksf + (uint32_t)((mt * 16 * ALDK + kk) * 4));
            ldsm_x4(bf[0][0], bf[0][1], bf[1][0], bf[1][1],
                    qsf + (uint32_t)(kk * 4));
            #pragma unroll
            for (int mt = 0; mt < 4; mt++)
                #pragma unroll
                for (int nt = 0; nt < 2; nt++)
                    mma_tf32(Sa[mt][nt], af[mt], bf[nt]);
        }

        // ---- mask + exp, write P tile (tf32), accumulate row sums
        const bool need_mask = (jt >= 2 * it);
        #pragma unroll
        for (int mt = 0; mt < 4; mt++) {
            #pragma unroll
            for (int nt = 0; nt < 2; nt++) {
                int rr0 = rbase + mt * 16 + gid;
                int cc = cbase + nt * 8 + 2 * tig;
                int iglob0 = i0 + rr0, iglob1 = iglob0 + 8;
                int jg = j0 + cc;
                float e0 = __expf(Sa[mt][nt][0] * scale);
                float e1 = __expf(Sa[mt][nt][1] * scale);
                float e2 = __expf(Sa[mt][nt][2] * scale);
                float e3 = __expf(Sa[mt][nt][3] * scale);
                if (need_mask) {
                    if (jg     > iglob0) e0 = 0.0f;
                    if (jg + 1 > iglob0) e1 = 0.0f;
                    if (jg     > iglob1) e2 = 0.0f;
                    if (jg + 1 > iglob1) e3 = 0.0f;
                }
                lacc[mt][0] += e0 + e1;
                lacc[mt][1] += e2 + e3;
                *(float2*)&ps[rr0 * ALDK + cc] =
                    make_float2(rnd_tf32(e0), rnd_tf32(e1));
                *(float2*)&ps[(rr0 + 8) * ALDK + cc] =
                    make_float2(rnd_tf32(e2), rnd_tf32(e3));
            }
        }
        CP_WAIT(0);          // vs(jt) arrived (hidden behind S-mma + exp)
        __syncthreads();     // P tile complete, vs visible

        // ---- O += P @ V  (M=128 i, N=64 p, K=64 j)
        #pragma unroll
        for (int kss = 0; kss < 8; kss++) {
            const int kk = kss * 8;
            uint32_t af[4][4], bf[2][2];
            #pragma unroll
            for (int mt = 0; mt < 4; mt++)
                ldsm_x4(af[mt][0], af[mt][1], af[mt][2], af[mt][3],
                        psf + (uint32_t)((mt * 16 * ALDK + kk) * 4));
            #pragma unroll
            for (int nt = 0; nt < 2; nt++) {
                int n = cbase + nt * 8 + gid;
                bf[nt][0] = __float_as_uint(vs[(kk + tig) * ALDV + n]);
                bf[nt][1] = __float_as_uint(vs[(kk + tig + 4) * ALDV + n]);
            }
            #pragma unroll
            for (int mt = 0; mt < 4; mt++)
                #pragma unroll
                for (int nt = 0; nt < 2; nt++)
                    mma_tf32(Oa[mt][nt], af[mt], bf[nt]);
        }

        if (jt + 1 < njt) {
            const int jn = (jt + 1) * 64;
            #pragma unroll
            for (int t = 0; t < 4; t++) {
                int idx = tid + t * 256;
                int r = idx >> 4, c4 = (idx & 15) * 4;
                cp_async16(&qs[r * ALDK + c4], &QVb[(size_t)(jn + r) * EE + c4]);
            }
        }
        CP_COMMIT();
    }

    #pragma unroll
    for (int mt = 0; mt < 4; mt++) {
        #pragma unroll
        for (int rr = 0; rr < 2; rr++) {
            float v = lacc[mt][rr];
            v += __shfl_xor_sync(0xffffffffu, v, 1);
            v += __shfl_xor_sync(0xffffffffu, v, 2);
            lacc[mt][rr] = v;
        }
    }
    __syncthreads();
    if (tig == 0) {
        #pragma unroll
        for (int mt = 0; mt < 4; mt++) {
            int r = rbase + mt * 16 + gid;
            lsm[r * 4 + wn] = lacc[mt][0];
            lsm[(r + 8) * 4 + wn] = lacc[mt][1];
        }
    }
    __syncthreads();

    float* Ab = g_At + (size_t)b * SS * EE + h * PP;
    #pragma unroll
    for (int mt = 0; mt < 4; mt++) {
        int r = rbase + mt * 16 + gid;
        float inv0 = 1.0f / (lsm[r * 4] + lsm[r * 4 + 1] + lsm[r * 4 + 2] + lsm[r * 4 + 3]);
        int r8 = r + 8;
        float inv1 = 1.0f / (lsm[r8 * 4] + lsm[r8 * 4 + 1] + lsm[r8 * 4 + 2] + lsm[r8 * 4 + 3]);
        #pragma unroll
        for (int nt = 0; nt < 2; nt++) {
            int c = cbase + nt * 8 + 2 * tig;
            *(float2*)&Ab[(size_t)(i0 + r) * EE + c] =
                make_float2(rnd_tf32(Oa[mt][nt][0] * inv0), rnd_tf32(Oa[mt][nt][1] * inv0));
            *(float2*)&Ab[(size_t)(i0 + r8) * EE + c] =
                make_float2(rnd_tf32(Oa[mt][nt][2] * inv1), rnd_tf32(Oa[mt][nt][3] * inv1));
        }
    }
}

// ---------------------------------------------------------------------------
extern "C" void kernel_launch(void* const* d_in, const int* in_sizes, int n_in,
                              void* d_out, int out_size)
{
    const float* x    = (const float*)d_in[0];
    const float* wk   = (const float*)d_in[1];
    const float* wv   = (const float*)d_in[2];
    const float* q    = (const float*)d_in[3];
    const float* lift = (const float*)d_in[4];
    float* out = (float*)d_out;

    static bool attr_done = false;
    if (!attr_done) {
        cudaFuncSetAttribute(proj_tf32_kernel,
            cudaFuncAttributeMaxDynamicSharedMemorySize, GEMM_SMEM);
        cudaFuncSetAttribute(lift_tf32_kernel,
            cudaFuncAttributeMaxDynamicSharedMemorySize, GEMM_SMEM);
        cudaFuncSetAttribute(qv_tf32_kernel,
            cudaFuncAttributeMaxDynamicSharedMemorySize, GEMM_SMEM);
        cudaFuncSetAttribute(attn_mma_kernel,
            cudaFuncAttributeMaxDynamicSharedMemorySize, ATT_SMEM);
        attr_done = true;
    }

    float *gK, *gV, *gAt, *gXt, *gQt, *gWkt, *gWvt, *gLtt;
    cudaGetSymbolAddress((void**)&gK,  g_K);
    cudaGetSymbolAddress((void**)&gV,  g_V);
    cudaGetSymbolAddress((void**)&gAt, g_At);
    cudaGetSymbolAddress((void**)&gXt, g_Xt);
    cudaGetSymbolAddress((void**)&gQt, g_Qt);
    cudaGetSymbolAddress((void**)&gWkt, g_Wkt);
    cudaGetSymbolAddress((void**)&gWvt, g_Wvt);
    cudaGetSymbolAddress((void**)&gLtt, g_Ltt);

    // --- prepass: ONE segmented tf32-rounding sweep
    round_all_kernel<<<(N4_TOT + 255) / 256, 256>>>(
        (const float4*)x, (const float4*)q, (const float4*)wk,
        (const float4*)wv, (const float4*)lift,
        (float4*)gXt, (float4*)gQt, (float4*)gWkt,
        (float4*)gWvt, (float4*)gLtt);

    const int M = BB * SS;

    // --- fused K/V projections (1536 CTAs @ 3/SM)
    dim3 gp(EE / BN, M / BM, 2);
    proj_tf32_kernel<<<gp, 256, GEMM_SMEM>>>(gXt, gWkt, gWvt, gK, gV);

    // --- QV = Q_h @ Vcat per head (768 CTAs @ 3/SM)
    dim3 gq((BB * PP) / BN, SS / BM, HH);
    qv_tf32_kernel<<<gq, 256, GEMM_SMEM>>>();

    // --- causal attention (tensor core)
    dim3 ga(SS / 128, HH, BB);
    attn_mma_kernel<<<ga, 256, ATT_SMEM>>>();

    // --- out = attn @ lifting (768 CTAs @ 3/SM, fp32 output)
    dim3 gl(EE / BN, M / BM);
    lift_tf32_kernel<<<gl, 256, GEMM_SMEM>>>(gAt, gLtt, out);
}